// round 1
// baseline (speedup 1.0000x reference)
#include <cuda_runtime.h>
#include <cuda_bf16.h>

#define BATCH 8
#define CC    64
#define HH    128
#define WW    128
#define HW    (HH*WW)

// ---------------- scratch (no allocation allowed -> __device__ globals) -----
__device__ float g_key0 [BATCH*CC*HW];
__device__ float g_query[BATCH*CC*HW];
__device__ float g_key  [BATCH*CC*HW];
__device__ float g_h0   [BATCH*CC*HW];
__device__ float g_h1   [BATCH*CC*HW];
__device__ float g_g    [BATCH*CC*HW];
__device__ float g_mid  [BATCH*32*HW];
__device__ float g_w72  [BATCH*72*HW];
__device__ float g_attn [BATCH*72*HW];

__device__ __forceinline__ float lrelu(float v) { return fmaxf(v, 0.1f*v); }

// ---------------- generic 1x1 conv (optionally concat of two inputs) --------
// block: 128 threads, each thread 4 consecutive pixels (float4).
// grid: (HW/512, BATCH). Weights staged in shared; CO_TILE accumulators so
// weight-LDS : FMA = 1:4 (below the 1 LDS/cyc/SM crossbar cap).
template<int CIN1, int CIN2, int COUT, bool LOUT>
__global__ void __launch_bounds__(128) pw_kernel(
    const float* __restrict__ in1, const float* __restrict__ in2,
    const float* __restrict__ Wt,  const float* __restrict__ bias,
    float* __restrict__ out)
{
    constexpr int CIN = CIN1 + CIN2;
    constexpr int COT = (COUT % 16 == 0) ? 16 : 8;
    __shared__ float sW[COUT*CIN];
    __shared__ float sB[COUT];
    const int tid = threadIdx.x;
    for (int i = tid; i < COUT*CIN/4; i += 128)
        reinterpret_cast<float4*>(sW)[i] = reinterpret_cast<const float4*>(Wt)[i];
    if (tid < COUT) sB[tid] = bias ? bias[tid] : 0.f;
    __syncthreads();

    const int b  = blockIdx.y;
    const int p0 = blockIdx.x * 512 + tid * 4;
    const float* b1 = in1 + (size_t)b*CIN1*HW + p0;
    const float* b2 = (CIN2 > 0) ? in2 + (size_t)b*CIN2*HW + p0 : nullptr;
    float* ob = out + (size_t)b*COUT*HW + p0;

    #pragma unroll 1
    for (int co0 = 0; co0 < COUT; co0 += COT) {
        float4 acc[COT];
        #pragma unroll
        for (int j = 0; j < COT; ++j) { float bv = sB[co0+j]; acc[j] = make_float4(bv,bv,bv,bv); }

        #pragma unroll 4
        for (int ci = 0; ci < CIN1; ++ci) {
            float4 xv = *reinterpret_cast<const float4*>(b1 + (size_t)ci*HW);
            #pragma unroll
            for (int j = 0; j < COT; ++j) {
                float wv = sW[(co0+j)*CIN + ci];
                acc[j].x = fmaf(wv, xv.x, acc[j].x);
                acc[j].y = fmaf(wv, xv.y, acc[j].y);
                acc[j].z = fmaf(wv, xv.z, acc[j].z);
                acc[j].w = fmaf(wv, xv.w, acc[j].w);
            }
        }
        if constexpr (CIN2 > 0) {
            #pragma unroll 4
            for (int ci = 0; ci < CIN2; ++ci) {
                float4 xv = *reinterpret_cast<const float4*>(b2 + (size_t)ci*HW);
                #pragma unroll
                for (int j = 0; j < COT; ++j) {
                    float wv = sW[(co0+j)*CIN + CIN1 + ci];
                    acc[j].x = fmaf(wv, xv.x, acc[j].x);
                    acc[j].y = fmaf(wv, xv.y, acc[j].y);
                    acc[j].z = fmaf(wv, xv.z, acc[j].z);
                    acc[j].w = fmaf(wv, xv.w, acc[j].w);
                }
            }
        }
        #pragma unroll
        for (int j = 0; j < COT; ++j) {
            float4 v = acc[j];
            if (LOUT) { v.x=lrelu(v.x); v.y=lrelu(v.y); v.z=lrelu(v.z); v.w=lrelu(v.w); }
            *reinterpret_cast<float4*>(ob + (size_t)(co0+j)*HW) = v;
        }
    }
}

// ---------------- grouped 3x3 conv (groups=4, 16in->16out) + lrelu ----------
// block 256 threads, tile 32x16 (each thread 2 pixels), shared halo tile.
__global__ void __launch_bounds__(256) gconv_kernel(
    const float* __restrict__ in, const float* __restrict__ ke,
    float* __restrict__ out)
{
    __shared__ float sIn[16][18][34];
    __shared__ float sW[16*16*9];
    const int tid = threadIdx.x;
    const int g = blockIdx.y, b = blockIdx.z;
    const int x0 = (blockIdx.x & 3) * 32;
    const int y0 = (blockIdx.x >> 2) * 16;
    const float* inb = in + ((size_t)(b*CC) + g*16) * HW;

    for (int i = tid; i < 2304/4; i += 256)
        reinterpret_cast<float4*>(sW)[i] =
            reinterpret_cast<const float4*>(ke + (size_t)g*2304)[i];

    for (int idx = tid; idx < 16*18*9; idx += 256) {
        int s = idx % 9, cr = idx / 9;
        int c = cr / 18, r = cr % 18;
        int gy = y0 - 1 + r;
        bool yok = ((unsigned)gy < 128u);
        const float* row = inb + (size_t)c*HW + gy*WW;
        if (s < 8) {
            int j = 1 + 4*s;
            float4 v = yok ? *reinterpret_cast<const float4*>(row + x0 + 4*s)
                           : make_float4(0,0,0,0);
            sIn[c][r][j]=v.x; sIn[c][r][j+1]=v.y; sIn[c][r][j+2]=v.z; sIn[c][r][j+3]=v.w;
        } else {
            sIn[c][r][0]  = (yok && x0-1  >= 0 ) ? row[x0-1]  : 0.f;
            sIn[c][r][33] = (yok && x0+32 < 128) ? row[x0+32] : 0.f;
        }
    }
    __syncthreads();

    const int tx = tid & 31, ty = tid >> 5;
    float accA[16], accB[16];
    #pragma unroll
    for (int co = 0; co < 16; ++co) { accA[co] = 0.f; accB[co] = 0.f; }

    #pragma unroll 1
    for (int ci = 0; ci < 16; ++ci) {
        #pragma unroll
        for (int kh = 0; kh < 3; ++kh) {
            float vA[3] = { sIn[ci][ty+kh][tx], sIn[ci][ty+kh][tx+1], sIn[ci][ty+kh][tx+2] };
            float vB[3] = { sIn[ci][ty+8+kh][tx], sIn[ci][ty+8+kh][tx+1], sIn[ci][ty+8+kh][tx+2] };
            #pragma unroll
            for (int kw = 0; kw < 3; ++kw) {
                #pragma unroll
                for (int co = 0; co < 16; ++co) {
                    float wv = sW[(co*16 + ci)*9 + kh*3 + kw];
                    accA[co] = fmaf(wv, vA[kw], accA[co]);
                    accB[co] = fmaf(wv, vB[kw], accB[co]);
                }
            }
        }
    }

    const int yA = y0 + ty, yB = y0 + ty + 8, x = x0 + tx;
    #pragma unroll
    for (int co = 0; co < 16; ++co) {
        float* op = out + ((size_t)(b*CC) + g*16 + co)*HW;
        op[yA*WW + x] = lrelu(accA[co]);
        op[yB*WW + x] = lrelu(accB[co]);
    }
}

// ---------------- per-pixel dynamic local conv (SHARE=8) -------------------
// out[b,c,y,x] = sum_tap in[b,c,y+kh-1,x+kw-1] * wb[b,(c/8)*9+tap,y,x] (+res)
// block 256 threads, tile 32x8; input staged per kernel-group in shared.
template<bool RES>
__global__ void __launch_bounds__(256) localconv_kernel(
    const float* __restrict__ in, const float* __restrict__ wb,
    const float* __restrict__ res, float* __restrict__ out)
{
    __shared__ float sh[8][10][34];
    const int tid = threadIdx.x;
    const int b  = blockIdx.y;
    const int x0 = (blockIdx.x & 3) * 32;
    const int y0 = (blockIdx.x >> 2) * 8;
    const int tx = tid & 31, ty = tid >> 5;
    const int pix = (y0 + ty)*WW + x0 + tx;

    const float* inb = in + (size_t)b*CC*HW;
    const float* wbb = wb + (size_t)b*72*HW + pix;
    float*       ob  = out + (size_t)b*CC*HW + pix;
    const float* rb  = RES ? res + (size_t)b*CC*HW + pix : nullptr;

    #pragma unroll 1
    for (int kg = 0; kg < 8; ++kg) {
        __syncthreads();
        const float* cb = inb + (size_t)kg*8*HW;
        for (int idx = tid; idx < 8*10*9; idx += 256) {
            int s = idx % 9, cr = idx / 9;
            int c = cr / 10, r = cr % 10;
            int gy = y0 - 1 + r;
            bool yok = ((unsigned)gy < 128u);
            const float* row = cb + (size_t)c*HW + gy*WW;
            if (s < 8) {
                int j = 1 + 4*s;
                float4 v = yok ? *reinterpret_cast<const float4*>(row + x0 + 4*s)
                               : make_float4(0,0,0,0);
                sh[c][r][j]=v.x; sh[c][r][j+1]=v.y; sh[c][r][j+2]=v.z; sh[c][r][j+3]=v.w;
            } else {
                sh[c][r][0]  = (yok && x0-1  >= 0 ) ? row[x0-1]  : 0.f;
                sh[c][r][33] = (yok && x0+32 < 128) ? row[x0+32] : 0.f;
            }
        }
        __syncthreads();

        float wv[9];
        #pragma unroll
        for (int t = 0; t < 9; ++t) wv[t] = wbb[(size_t)(kg*9 + t)*HW];

        #pragma unroll
        for (int c = 0; c < 8; ++c) {
            int ch = kg*8 + c;
            float acc = RES ? rb[(size_t)ch*HW] : 0.f;
            #pragma unroll
            for (int kh = 0; kh < 3; ++kh)
                #pragma unroll
                for (int kw = 0; kw < 3; ++kw)
                    acc = fmaf(sh[c][ty+kh][tx+kw], wv[kh*3+kw], acc);
            ob[(size_t)ch*HW] = acc;
        }
    }
}

// ---------------- softmax over H (axis=2 of [B,72,H,W]) --------------------
// one block per (channel, batch); thread = W column -> coalesced strided loads.
__global__ void __launch_bounds__(128) softmax_h(float* __restrict__ a)
{
    const int ch = blockIdx.x, b = blockIdx.y;
    float* col = a + ((size_t)(b*72) + ch)*HW + threadIdx.x;
    float m = -1e30f;
    #pragma unroll 4
    for (int h = 0; h < 128; ++h) m = fmaxf(m, col[h*WW]);
    float s = 0.f;
    #pragma unroll 4
    for (int h = 0; h < 128; ++h) s += __expf(col[h*WW] - m);
    float inv = 1.f / s;
    #pragma unroll 4
    for (int h = 0; h < 128; ++h) col[h*WW] = __expf(col[h*WW] - m) * inv;
}

// ---------------- launch --------------------------------------------------
extern "C" void kernel_launch(void* const* d_in, const int* in_sizes, int n_in,
                              void* d_out, int out_size)
{
    (void)in_sizes; (void)n_in; (void)out_size;
    const float* x      = (const float*)d_in[0];
    const float* phi_w  = (const float*)d_in[1];
    const float* phi_b  = (const float*)d_in[2];
    const float* th_w   = (const float*)d_in[3];
    const float* th_b   = (const float*)d_in[4];
    const float* ke_w   = (const float*)d_in[5];
    const float* e1_w   = (const float*)d_in[6];
    const float* e2_w   = (const float*)d_in[7];
    const float* e2_b   = (const float*)d_in[8];
    const float* c1_w   = (const float*)d_in[9];
    const float* sw1_w  = (const float*)d_in[10];
    const float* sw2_w  = (const float*)d_in[11];
    const float* sw2_b  = (const float*)d_in[12];
    const float* sec_w  = (const float*)d_in[13];
    const float* sec_b  = (const float*)d_in[14];

    float *key0, *query, *key, *h0, *h1, *mid, *w72, *attn, *gg;
    cudaGetSymbolAddress((void**)&key0,  g_key0);
    cudaGetSymbolAddress((void**)&query, g_query);
    cudaGetSymbolAddress((void**)&key,   g_key);
    cudaGetSymbolAddress((void**)&h0,    g_h0);
    cudaGetSymbolAddress((void**)&h1,    g_h1);
    cudaGetSymbolAddress((void**)&mid,   g_mid);
    cudaGetSymbolAddress((void**)&w72,   g_w72);
    cudaGetSymbolAddress((void**)&attn,  g_attn);
    cudaGetSymbolAddress((void**)&gg,    g_g);

    dim3 pwg(HW/512, BATCH);

    // key0 = phi(x), query = theta(x), h0 = c1(x)
    pw_kernel<64,0,64,false><<<pwg,128>>>(x, nullptr, phi_w, phi_b, key0);
    pw_kernel<64,0,64,false><<<pwg,128>>>(x, nullptr, th_w,  th_b,  query);
    pw_kernel<64,0,64,false><<<pwg,128>>>(x, nullptr, c1_w,  nullptr, h0);

    // key = lrelu(grouped3x3(key0))
    gconv_kernel<<<dim3(32,4,BATCH),256>>>(key0, ke_w, key);

    // w = e2(lrelu(e1([query,key])))
    pw_kernel<64,64,32,true ><<<pwg,128>>>(query, key, e1_w, nullptr, mid);
    pw_kernel<32,0,72,false><<<pwg,128>>>(mid, nullptr, e2_w, e2_b, w72);

    // h1 = local_conv(h0, w)
    localconv_kernel<false><<<dim3(64,BATCH),256>>>(h0, w72, nullptr, h1);

    // attn = softmax_H(sw2(lrelu(sw1([h1,key]))))
    pw_kernel<64,64,32,true ><<<pwg,128>>>(h1, key, sw1_w, nullptr, mid);
    pw_kernel<32,0,72,false><<<pwg,128>>>(mid, nullptr, sw2_w, sw2_b, attn);
    softmax_h<<<dim3(72,BATCH),128>>>(attn);

    // out = local_conv(sec([h1,key]), attn) + x
    pw_kernel<64,64,64,false><<<pwg,128>>>(h1, key, sec_w, sec_b, gg);
    localconv_kernel<true><<<dim3(64,BATCH),256>>>(gg, attn, x, (float*)d_out);
}

// round 2
// speedup vs baseline: 1.1071x; 1.1071x over previous
#include <cuda_runtime.h>
#include <cuda_bf16.h>

#define BATCH 8
#define CC    64
#define HH    128
#define WW    128
#define HW    (HH*WW)

typedef unsigned long long u64;

// ---------------- f32x2 packed helpers (sm_100+) ---------------------------
__device__ __forceinline__ u64 pk2(float a, float b) {
    u64 r; asm("mov.b64 %0,{%1,%2};" : "=l"(r) : "f"(a), "f"(b)); return r;
}
__device__ __forceinline__ u64 splat2(float a) {
    u64 r; asm("mov.b64 %0,{%1,%1};" : "=l"(r) : "f"(a)); return r;
}
__device__ __forceinline__ u64 ffma2(u64 a, u64 b, u64 c) {
    u64 d; asm("fma.rn.f32x2 %0,%1,%2,%3;" : "=l"(d) : "l"(a), "l"(b), "l"(c)); return d;
}
__device__ __forceinline__ float2 upk(u64 v) {
    float2 f; asm("mov.b64 {%0,%1},%2;" : "=f"(f.x), "=f"(f.y) : "l"(v)); return f;
}
__device__ __forceinline__ float lrelu(float v) { return fmaxf(v, 0.1f*v); }

// ---------------- scratch --------------------------------------------------
__device__ float g_key0 [BATCH*CC*HW];
__device__ float g_query[BATCH*CC*HW];
__device__ float g_key  [BATCH*CC*HW];
__device__ float g_h0   [BATCH*CC*HW];
__device__ float g_h1   [BATCH*CC*HW];
__device__ float g_g    [BATCH*CC*HW];
__device__ float g_mid  [BATCH*32*HW];
__device__ float g_w72  [BATCH*72*HW];
__device__ float g_attn [BATCH*72*HW];

// ---------------- 1x1 conv, FFMA2, co-pair packing -------------------------
// block 128 threads, thread = 4 pixels. Weights staged transposed [ci][co]
// (padded stride) so each ci gives vector LDS.128 broadcast loads of co-pairs.
template<int CIN1, int CIN2, int COUT, bool LOUT>
__global__ void __launch_bounds__(128) pw2_kernel(
    const float* __restrict__ in1, const float* __restrict__ in2,
    const float* __restrict__ Wt,  const float* __restrict__ bias,
    float* __restrict__ out)
{
    constexpr int CIN = CIN1 + CIN2;
    constexpr int COT = (COUT % 16 == 0) ? 16 : 8;
    constexpr int NP  = COT / 2;
    constexpr int STR = COUT + 4;                 // padded row (16B aligned)
    __shared__ float sW[CIN*STR];
    __shared__ float sB[COUT];
    const int tid = threadIdx.x;
    for (int i = tid; i < COUT*CIN; i += 128) {
        int co = i / CIN, ci = i - co*CIN;
        sW[ci*STR + co] = Wt[i];
    }
    if (tid < COUT) sB[tid] = bias ? bias[tid] : 0.f;
    __syncthreads();

    const int b  = blockIdx.y;
    const int p0 = blockIdx.x * 512 + tid * 4;
    const float* b1 = in1 + (size_t)b*CIN1*HW + p0;
    const float* b2 = (CIN2 > 0) ? in2 + (size_t)b*CIN2*HW + p0 : nullptr;
    float* ob = out + (size_t)b*COUT*HW + p0;

    #pragma unroll 1
    for (int co0 = 0; co0 < COUT; co0 += COT) {
        u64 acc[4][NP];
        #pragma unroll
        for (int j = 0; j < NP; ++j) {
            u64 bv = pk2(sB[co0+2*j], sB[co0+2*j+1]);
            acc[0][j]=bv; acc[1][j]=bv; acc[2][j]=bv; acc[3][j]=bv;
        }

        #pragma unroll 4
        for (int ci = 0; ci < CIN1; ++ci) {
            float4 xv = *reinterpret_cast<const float4*>(b1 + (size_t)ci*HW);
            u64 s0=splat2(xv.x), s1=splat2(xv.y), s2=splat2(xv.z), s3=splat2(xv.w);
            const float* wr = &sW[ci*STR + co0];
            #pragma unroll
            for (int j = 0; j < NP; j += 2) {
                float4 w4 = *reinterpret_cast<const float4*>(wr + 2*j);
                u64 wp0 = pk2(w4.x, w4.y), wp1 = pk2(w4.z, w4.w);
                acc[0][j]  =ffma2(s0,wp0,acc[0][j]);   acc[0][j+1]=ffma2(s0,wp1,acc[0][j+1]);
                acc[1][j]  =ffma2(s1,wp0,acc[1][j]);   acc[1][j+1]=ffma2(s1,wp1,acc[1][j+1]);
                acc[2][j]  =ffma2(s2,wp0,acc[2][j]);   acc[2][j+1]=ffma2(s2,wp1,acc[2][j+1]);
                acc[3][j]  =ffma2(s3,wp0,acc[3][j]);   acc[3][j+1]=ffma2(s3,wp1,acc[3][j+1]);
            }
        }
        if constexpr (CIN2 > 0) {
            #pragma unroll 4
            for (int ci = 0; ci < CIN2; ++ci) {
                float4 xv = *reinterpret_cast<const float4*>(b2 + (size_t)ci*HW);
                u64 s0=splat2(xv.x), s1=splat2(xv.y), s2=splat2(xv.z), s3=splat2(xv.w);
                const float* wr = &sW[(CIN1+ci)*STR + co0];
                #pragma unroll
                for (int j = 0; j < NP; j += 2) {
                    float4 w4 = *reinterpret_cast<const float4*>(wr + 2*j);
                    u64 wp0 = pk2(w4.x, w4.y), wp1 = pk2(w4.z, w4.w);
                    acc[0][j]  =ffma2(s0,wp0,acc[0][j]);   acc[0][j+1]=ffma2(s0,wp1,acc[0][j+1]);
                    acc[1][j]  =ffma2(s1,wp0,acc[1][j]);   acc[1][j+1]=ffma2(s1,wp1,acc[1][j+1]);
                    acc[2][j]  =ffma2(s2,wp0,acc[2][j]);   acc[2][j+1]=ffma2(s2,wp1,acc[2][j+1]);
                    acc[3][j]  =ffma2(s3,wp0,acc[3][j]);   acc[3][j+1]=ffma2(s3,wp1,acc[3][j+1]);
                }
            }
        }

        #pragma unroll
        for (int j = 0; j < NP; ++j) {
            float2 v0=upk(acc[0][j]), v1=upk(acc[1][j]), v2=upk(acc[2][j]), v3=upk(acc[3][j]);
            float4 olo = make_float4(v0.x, v1.x, v2.x, v3.x);
            float4 ohi = make_float4(v0.y, v1.y, v2.y, v3.y);
            if (LOUT) {
                olo.x=lrelu(olo.x); olo.y=lrelu(olo.y); olo.z=lrelu(olo.z); olo.w=lrelu(olo.w);
                ohi.x=lrelu(ohi.x); ohi.y=lrelu(ohi.y); ohi.z=lrelu(ohi.z); ohi.w=lrelu(ohi.w);
            }
            *reinterpret_cast<float4*>(ob + (size_t)(co0+2*j  )*HW) = olo;
            *reinterpret_cast<float4*>(ob + (size_t)(co0+2*j+1)*HW) = ohi;
        }
    }
}

// ---------------- grouped 3x3 conv (groups=4) + lrelu, FFMA2 ---------------
// Weights staged [ci][kh][kw][co] -> per-tap vector LDS.128 broadcast loads.
// Thread = 2 pixels (y, y+8); accumulators packed over co-pairs.
__global__ void __launch_bounds__(256) gconv2_kernel(
    const float* __restrict__ in, const float* __restrict__ ke,
    float* __restrict__ out)
{
    __shared__ float sIn[16][18][34];
    __shared__ float sWt[16*9*16];     // [ci][tap][co]
    const int tid = threadIdx.x;
    const int g = blockIdx.y, b = blockIdx.z;
    const int x0 = (blockIdx.x & 3) * 32;
    const int y0 = (blockIdx.x >> 2) * 16;
    const float* inb = in + ((size_t)(b*CC) + g*16) * HW;
    const float* kep = ke + (size_t)g*2304;

    for (int i = tid; i < 2304; i += 256) {
        int co = i / 144, rem = i - co*144;
        int ci = rem / 9,  t  = rem - ci*9;
        sWt[(ci*9 + t)*16 + co] = kep[i];
    }

    for (int idx = tid; idx < 16*18*9; idx += 256) {
        int s = idx % 9, cr = idx / 9;
        int c = cr / 18, r = cr % 18;
        int gy = y0 - 1 + r;
        bool yok = ((unsigned)gy < 128u);
        const float* row = inb + (size_t)c*HW + gy*WW;
        if (s < 8) {
            int j = 1 + 4*s;
            float4 v = yok ? *reinterpret_cast<const float4*>(row + x0 + 4*s)
                           : make_float4(0,0,0,0);
            sIn[c][r][j]=v.x; sIn[c][r][j+1]=v.y; sIn[c][r][j+2]=v.z; sIn[c][r][j+3]=v.w;
        } else {
            sIn[c][r][0]  = (yok && x0-1  >= 0 ) ? row[x0-1]  : 0.f;
            sIn[c][r][33] = (yok && x0+32 < 128) ? row[x0+32] : 0.f;
        }
    }
    __syncthreads();

    const int tx = tid & 31, ty = tid >> 5;
    u64 accA[8], accB[8];
    #pragma unroll
    for (int j = 0; j < 8; ++j) { accA[j] = 0ull; accB[j] = 0ull; }

    #pragma unroll 1
    for (int ci = 0; ci < 16; ++ci) {
        #pragma unroll
        for (int kh = 0; kh < 3; ++kh) {
            u64 As[3] = { splat2(sIn[ci][ty+kh][tx]),  splat2(sIn[ci][ty+kh][tx+1]),  splat2(sIn[ci][ty+kh][tx+2]) };
            u64 Bs[3] = { splat2(sIn[ci][ty+8+kh][tx]),splat2(sIn[ci][ty+8+kh][tx+1]),splat2(sIn[ci][ty+8+kh][tx+2]) };
            const float* wb = &sWt[(ci*9 + kh*3)*16];
            #pragma unroll
            for (int kw = 0; kw < 3; ++kw) {
                const float* w = wb + kw*16;
                #pragma unroll
                for (int jp = 0; jp < 8; jp += 2) {
                    float4 w4 = *reinterpret_cast<const float4*>(w + 2*jp);
                    u64 wp0 = pk2(w4.x, w4.y), wp1 = pk2(w4.z, w4.w);
                    accA[jp]   = ffma2(As[kw], wp0, accA[jp]);
                    accA[jp+1] = ffma2(As[kw], wp1, accA[jp+1]);
                    accB[jp]   = ffma2(Bs[kw], wp0, accB[jp]);
                    accB[jp+1] = ffma2(Bs[kw], wp1, accB[jp+1]);
                }
            }
        }
    }

    const int yA = y0 + ty, yB = y0 + ty + 8, x = x0 + tx;
    #pragma unroll
    for (int jp = 0; jp < 8; ++jp) {
        float2 a = upk(accA[jp]), bb = upk(accB[jp]);
        float* op0 = out + ((size_t)(b*CC) + g*16 + 2*jp  )*HW;
        float* op1 = out + ((size_t)(b*CC) + g*16 + 2*jp+1)*HW;
        op0[yA*WW + x] = lrelu(a.x);
        op1[yA*WW + x] = lrelu(a.y);
        op0[yB*WW + x] = lrelu(bb.x);
        op1[yB*WW + x] = lrelu(bb.y);
    }
}

// ---------------- per-pixel dynamic local conv (SHARE=8), FFMA2 ------------
template<bool RES>
__global__ void __launch_bounds__(256) localconv2_kernel(
    const float* __restrict__ in, const float* __restrict__ wb,
    const float* __restrict__ res, float* __restrict__ out)
{
    __shared__ float sh[8][10][34];
    const int tid = threadIdx.x;
    const int b  = blockIdx.y;
    const int x0 = (blockIdx.x & 3) * 32;
    const int y0 = (blockIdx.x >> 2) * 8;
    const int tx = tid & 31, ty = tid >> 5;
    const int pix = (y0 + ty)*WW + x0 + tx;

    const float* inb = in + (size_t)b*CC*HW;
    const float* wbb = wb + (size_t)b*72*HW + pix;
    float*       ob  = out + (size_t)b*CC*HW + pix;
    const float* rb  = RES ? res + (size_t)b*CC*HW + pix : nullptr;

    #pragma unroll 1
    for (int kg = 0; kg < 8; ++kg) {
        __syncthreads();
        const float* cb = inb + (size_t)kg*8*HW;
        for (int idx = tid; idx < 8*10*9; idx += 256) {
            int s = idx % 9, cr = idx / 9;
            int c = cr / 10, r = cr % 10;
            int gy = y0 - 1 + r;
            bool yok = ((unsigned)gy < 128u);
            const float* row = cb + (size_t)c*HW + gy*WW;
            if (s < 8) {
                int j = 1 + 4*s;
                float4 v = yok ? *reinterpret_cast<const float4*>(row + x0 + 4*s)
                               : make_float4(0,0,0,0);
                sh[c][r][j]=v.x; sh[c][r][j+1]=v.y; sh[c][r][j+2]=v.z; sh[c][r][j+3]=v.w;
            } else {
                sh[c][r][0]  = (yok && x0-1  >= 0 ) ? row[x0-1]  : 0.f;
                sh[c][r][33] = (yok && x0+32 < 128) ? row[x0+32] : 0.f;
            }
        }
        __syncthreads();

        u64 ws[9];
        #pragma unroll
        for (int t = 0; t < 9; ++t) ws[t] = splat2(wbb[(size_t)(kg*9 + t)*HW]);

        #pragma unroll
        for (int cp = 0; cp < 4; ++cp) {
            const int c0 = 2*cp, ch = kg*8 + c0;
            u64 acc = RES ? pk2(rb[(size_t)ch*HW], rb[(size_t)(ch+1)*HW]) : 0ull;
            #pragma unroll
            for (int kh = 0; kh < 3; ++kh)
                #pragma unroll
                for (int kw = 0; kw < 3; ++kw) {
                    u64 a = pk2(sh[c0][ty+kh][tx+kw], sh[c0+1][ty+kh][tx+kw]);
                    acc = ffma2(a, ws[kh*3+kw], acc);
                }
            float2 r = upk(acc);
            ob[(size_t)ch*HW]     = r.x;
            ob[(size_t)(ch+1)*HW] = r.y;
        }
    }
}

// ---------------- softmax over H (axis=2 of [B,72,H,W]) --------------------
__global__ void __launch_bounds__(128) softmax_h(float* __restrict__ a)
{
    const int ch = blockIdx.x, b = blockIdx.y;
    float* col = a + ((size_t)(b*72) + ch)*HW + threadIdx.x;
    float m = -1e30f;
    #pragma unroll 4
    for (int h = 0; h < 128; ++h) m = fmaxf(m, col[h*WW]);
    float s = 0.f;
    #pragma unroll 4
    for (int h = 0; h < 128; ++h) s += __expf(col[h*WW] - m);
    float inv = 1.f / s;
    #pragma unroll 4
    for (int h = 0; h < 128; ++h) col[h*WW] = __expf(col[h*WW] - m) * inv;
}

// ---------------- launch --------------------------------------------------
extern "C" void kernel_launch(void* const* d_in, const int* in_sizes, int n_in,
                              void* d_out, int out_size)
{
    (void)in_sizes; (void)n_in; (void)out_size;
    const float* x      = (const float*)d_in[0];
    const float* phi_w  = (const float*)d_in[1];
    const float* phi_b  = (const float*)d_in[2];
    const float* th_w   = (const float*)d_in[3];
    const float* th_b   = (const float*)d_in[4];
    const float* ke_w   = (const float*)d_in[5];
    const float* e1_w   = (const float*)d_in[6];
    const float* e2_w   = (const float*)d_in[7];
    const float* e2_b   = (const float*)d_in[8];
    const float* c1_w   = (const float*)d_in[9];
    const float* sw1_w  = (const float*)d_in[10];
    const float* sw2_w  = (const float*)d_in[11];
    const float* sw2_b  = (const float*)d_in[12];
    const float* sec_w  = (const float*)d_in[13];
    const float* sec_b  = (const float*)d_in[14];

    float *key0, *query, *key, *h0, *h1, *mid, *w72, *attn, *gg;
    cudaGetSymbolAddress((void**)&key0,  g_key0);
    cudaGetSymbolAddress((void**)&query, g_query);
    cudaGetSymbolAddress((void**)&key,   g_key);
    cudaGetSymbolAddress((void**)&h0,    g_h0);
    cudaGetSymbolAddress((void**)&h1,    g_h1);
    cudaGetSymbolAddress((void**)&mid,   g_mid);
    cudaGetSymbolAddress((void**)&w72,   g_w72);
    cudaGetSymbolAddress((void**)&attn,  g_attn);
    cudaGetSymbolAddress((void**)&gg,    g_g);

    dim3 pwg(HW/512, BATCH);

    // key0 = phi(x), query = theta(x), h0 = c1(x)
    pw2_kernel<64,0,64,false><<<pwg,128>>>(x, nullptr, phi_w, phi_b, key0);
    pw2_kernel<64,0,64,false><<<pwg,128>>>(x, nullptr, th_w,  th_b,  query);
    pw2_kernel<64,0,64,false><<<pwg,128>>>(x, nullptr, c1_w,  nullptr, h0);

    // key = lrelu(grouped3x3(key0))
    gconv2_kernel<<<dim3(32,4,BATCH),256>>>(key0, ke_w, key);

    // w = e2(lrelu(e1([query,key])))
    pw2_kernel<64,64,32,true ><<<pwg,128>>>(query, key, e1_w, nullptr, mid);
    pw2_kernel<32,0,72,false><<<pwg,128>>>(mid, nullptr, e2_w, e2_b, w72);

    // h1 = local_conv(h0, w)
    localconv2_kernel<false><<<dim3(64,BATCH),256>>>(h0, w72, nullptr, h1);

    // attn = softmax_H(sw2(lrelu(sw1([h1,key]))))
    pw2_kernel<64,64,32,true ><<<pwg,128>>>(h1, key, sw1_w, nullptr, mid);
    pw2_kernel<32,0,72,false><<<pwg,128>>>(mid, nullptr, sw2_w, sw2_b, attn);
    softmax_h<<<dim3(72,BATCH),128>>>(attn);

    // out = local_conv(sec([h1,key]), attn) + x
    pw2_kernel<64,64,64,false><<<pwg,128>>>(h1, key, sec_w, sec_b, gg);
    localconv2_kernel<true><<<dim3(64,BATCH),256>>>(gg, attn, x, (float*)d_out);
}

// round 9
// speedup vs baseline: 1.3001x; 1.1744x over previous
#include <cuda_runtime.h>
#include <cuda_bf16.h>
#include <cstdint>

#define BATCH 8
#define CC    64
#define WW    128
#define HW    16384
typedef unsigned long long u64;
typedef unsigned int u32;
typedef __nv_bfloat16 bf16;

// ---------------- helpers ---------------------------------------------------
__device__ __forceinline__ u32 smem_u32(const void* p) {
    u32 a; asm("{ .reg .u64 t; cvta.to.shared.u64 t, %1; cvt.u32.u64 %0, t; }" : "=r"(a) : "l"(p)); return a;
}
__device__ __forceinline__ float lrelu(float v) { return fmaxf(v, 0.1f*v); }
__device__ __forceinline__ void split1(float v, bf16& h, bf16& l) {
    h = __float2bfloat16(v); l = __float2bfloat16(v - __bfloat162float(h));
}
__device__ __forceinline__ void split2(float a, float b, u32& h, u32& l) {
    bf16 ah,al,bh,bl; split1(a,ah,al); split1(b,bh,bl);
    __nv_bfloat162 H = __halves2bfloat162(ah,bh), L = __halves2bfloat162(al,bl);
    h = *(u32*)&H; l = *(u32*)&L;
}

#define LDMX4(r, addr) asm volatile( \
    "ldmatrix.sync.aligned.m8n8.x4.shared.b16 {%0,%1,%2,%3}, [%4];" \
    : "=r"((r)[0]),"=r"((r)[1]),"=r"((r)[2]),"=r"((r)[3]) : "r"(addr))

#define MMA16(d, a, b0, b1) asm volatile( \
    "mma.sync.aligned.m16n8k16.row.col.f32.bf16.bf16.f32 " \
    "{%0,%1,%2,%3},{%4,%5,%6,%7},{%8,%9},{%0,%1,%2,%3};" \
    : "+f"((d)[0]),"+f"((d)[1]),"+f"((d)[2]),"+f"((d)[3]) \
    : "r"((a)[0]),"r"((a)[1]),"r"((a)[2]),"r"((a)[3]), "r"(b0),"r"(b1))

// ---------------- scratch ---------------------------------------------------
__device__ float g_key0[BATCH*CC*HW];
__device__ float g_h0  [BATCH*CC*HW];
__device__ float g_gg  [BATCH*CC*HW];
__device__ float g_w72 [BATCH*72*HW];
__device__ float g_attn[BATCH*72*HW];
__device__ bf16 g_xh[BATCH*CC*HW],  g_xl[BATCH*CC*HW];
__device__ bf16 g_qh[BATCH*CC*HW],  g_ql[BATCH*CC*HW];
__device__ bf16 g_kh[BATCH*CC*HW],  g_kl[BATCH*CC*HW];
__device__ bf16 g_hh[BATCH*CC*HW],  g_hl[BATCH*CC*HW];
__device__ bf16 g_mh[BATCH*32*HW],  g_ml[BATCH*32*HW];

// ---------------- prep: x -> bf16 hi/lo -------------------------------------
__global__ void __launch_bounds__(512) prep_x(const float* __restrict__ x,
                                              bf16* __restrict__ xh, bf16* __restrict__ xl)
{
    int i = blockIdx.x*512 + threadIdx.x;
    float4 v = reinterpret_cast<const float4*>(x)[i];
    u32 h0,l0,h1,l1; split2(v.x,v.y,h0,l0); split2(v.z,v.w,h1,l1);
    reinterpret_cast<uint2*>(xh)[i] = make_uint2(h0,h1);
    reinterpret_cast<uint2*>(xl)[i] = make_uint2(l0,l1);
}

// ---------------- HMMA pointwise GEMM ---------------------------------------
// D[COUT, 128px] = W[COUT,CIN] x [in1;in2], bf16 split-3 via mma.sync.
// smem X transposed [px][cinpair] (u32 = bf16x2), pad CINP2 for conflict-free.
template<int C1, int C2, int COUT, int MT, int NWARP, bool LRELU, bool SPLIT>
__global__ void __launch_bounds__(NWARP*32, 1) pw_hmma(
    const bf16* __restrict__ p1h, const bf16* __restrict__ p1l,
    const bf16* __restrict__ p2h, const bf16* __restrict__ p2l,
    const float* __restrict__ Wt, const float* __restrict__ bias,
    float* __restrict__ of, bf16* __restrict__ oh, bf16* __restrict__ ol)
{
    constexpr int CIN = C1 + C2, KP2 = CIN/2;
    constexpr int CINP2 = (CIN == 128) ? 68 : (CIN == 64) ? 36 : 20;
    constexpr int COP = MT*16, NTH = NWARP*32, KS = CIN/16;

    extern __shared__ u32 sm[];
    u32* XH = sm;
    u32* XL = XH + 128*CINP2;
    u32* WH = XL + 128*CINP2;
    u32* WL = WH + COP*CINP2;
    float* SB = (float*)(WL + COP*CINP2);

    const int tid = threadIdx.x, lane = tid & 31, wid = tid >> 5;
    const int b = blockIdx.y;
    const int pxb = blockIdx.x * 128;

    // ---- stage X (transpose ch-major -> [px][cinpair]) ----
    for (int chunk = wid; chunk < 16; chunk += NWARP) {
        for (int cp = lane; cp < KP2; cp += 32) {
            int ch = 2*cp;
            const bf16 *ph, *pl;
            if (ch < C1) { size_t o = ((size_t)b*C1 + ch)*HW + pxb + chunk*8; ph = p1h + o; pl = p1l + o; }
            else         { size_t o = ((size_t)b*C2 + (ch-C1))*HW + pxb + chunk*8; ph = p2h + o; pl = p2l + o; }
            uint4 a0 = *(const uint4*)ph, a1 = *(const uint4*)(ph + HW);
            uint4 c0 = *(const uint4*)pl, c1 = *(const uint4*)(pl + HW);
            u32* dh = &XH[(chunk*8)*CINP2 + cp];
            u32* dl = &XL[(chunk*8)*CINP2 + cp];
            dh[0*CINP2] = __byte_perm(a0.x, a1.x, 0x5410); dh[1*CINP2] = __byte_perm(a0.x, a1.x, 0x7632);
            dh[2*CINP2] = __byte_perm(a0.y, a1.y, 0x5410); dh[3*CINP2] = __byte_perm(a0.y, a1.y, 0x7632);
            dh[4*CINP2] = __byte_perm(a0.z, a1.z, 0x5410); dh[5*CINP2] = __byte_perm(a0.z, a1.z, 0x7632);
            dh[6*CINP2] = __byte_perm(a0.w, a1.w, 0x5410); dh[7*CINP2] = __byte_perm(a0.w, a1.w, 0x7632);
            dl[0*CINP2] = __byte_perm(c0.x, c1.x, 0x5410); dl[1*CINP2] = __byte_perm(c0.x, c1.x, 0x7632);
            dl[2*CINP2] = __byte_perm(c0.y, c1.y, 0x5410); dl[3*CINP2] = __byte_perm(c0.y, c1.y, 0x7632);
            dl[4*CINP2] = __byte_perm(c0.z, c1.z, 0x5410); dl[5*CINP2] = __byte_perm(c0.z, c1.z, 0x7632);
            dl[6*CINP2] = __byte_perm(c0.w, c1.w, 0x5410); dl[7*CINP2] = __byte_perm(c0.w, c1.w, 0x7632);
        }
    }
    // ---- stage W (fp32 -> split bf16 pairs) ----
    for (int i = tid; i < COP*KP2; i += NTH) {
        int co = i / KP2, cp = i - co*KP2;
        float2 wv = make_float2(0.f, 0.f);
        if (co < COUT) wv = *(const float2*)(Wt + (size_t)co*CIN + 2*cp);
        u32 H, L; split2(wv.x, wv.y, H, L);
        WH[co*CINP2 + cp] = H; WL[co*CINP2 + cp] = L;
    }
    if (tid < COP) SB[tid] = (bias && tid < COUT) ? bias[tid] : 0.f;
    __syncthreads();

    // ---- main loop ----
    const int mt = wid % MT, nh = wid / MT;
    const int co0 = mt*16, pn0 = nh*64;
    float acc[8][4];
    #pragma unroll
    for (int n = 0; n < 8; ++n) { acc[n][0]=0.f; acc[n][1]=0.f; acc[n][2]=0.f; acc[n][3]=0.f; }

    const int arow = co0 + (lane & 7) + ((lane >> 3) & 1)*8;
    const int acw  = ((lane >> 4) & 1)*4;
    const u32 aBH = smem_u32(&WH[arow*CINP2 + acw]);
    const u32 aBL = smem_u32(&WL[arow*CINP2 + acw]);
    const int brow = pn0 + (lane >> 2), bcol = lane & 3;
    const u32* bXH = &XH[brow*CINP2 + bcol];
    const u32* bXL = &XL[brow*CINP2 + bcol];

    #pragma unroll
    for (int ks = 0; ks < KS; ++ks) {
        u32 Ah[4], Al[4];
        LDMX4(Ah, aBH + ks*32);
        LDMX4(Al, aBL + ks*32);
        #pragma unroll
        for (int nt = 0; nt < 8; ++nt) {
            u32 bh0 = bXH[nt*8*CINP2 + ks*8];
            u32 bh1 = bXH[nt*8*CINP2 + ks*8 + 4];
            u32 bl0 = bXL[nt*8*CINP2 + ks*8];
            u32 bl1 = bXL[nt*8*CINP2 + ks*8 + 4];
            MMA16(acc[nt], Ah, bh0, bh1);
            MMA16(acc[nt], Ah, bl0, bl1);
            MMA16(acc[nt], Al, bh0, bh1);
        }
    }

    // ---- epilogue: rows = channels, cols = pixels (direct stores) ----
    const int g = lane >> 2, c = lane & 3;
    const int coA = co0 + g, coB = coA + 8;
    const float bvA = SB[coA], bvB = SB[coB];
    #pragma unroll
    for (int nt = 0; nt < 8; ++nt) {
        int px = pxb + pn0 + nt*8 + 2*c;
        float v0 = acc[nt][0] + bvA, v1 = acc[nt][1] + bvA;
        float v2 = acc[nt][2] + bvB, v3 = acc[nt][3] + bvB;
        if (LRELU) { v0=lrelu(v0); v1=lrelu(v1); v2=lrelu(v2); v3=lrelu(v3); }
        if (SPLIT) {
            if (coA < COUT) {
                u32 H,L; split2(v0,v1,H,L);
                size_t o = ((size_t)b*COUT + coA)*HW + px;
                *(u32*)(oh + o) = H; *(u32*)(ol + o) = L;
            }
            if (coB < COUT) {
                u32 H,L; split2(v2,v3,H,L);
                size_t o = ((size_t)b*COUT + coB)*HW + px;
                *(u32*)(oh + o) = H; *(u32*)(ol + o) = L;
            }
        } else {
            if (coA < COUT) *(float2*)(of + ((size_t)b*COUT + coA)*HW + px) = make_float2(v0,v1);
            if (coB < COUT) *(float2*)(of + ((size_t)b*COUT + coB)*HW + px) = make_float2(v2,v3);
        }
    }
}

// ---------------- FFMA2 helpers for conv kernels ----------------------------
__device__ __forceinline__ u64 pk2(float a, float b) { u64 r; asm("mov.b64 %0,{%1,%2};" : "=l"(r) : "f"(a), "f"(b)); return r; }
__device__ __forceinline__ u64 splat2(float a) { u64 r; asm("mov.b64 %0,{%1,%1};" : "=l"(r) : "f"(a)); return r; }
__device__ __forceinline__ u64 ffma2(u64 a, u64 b, u64 c) { u64 d; asm("fma.rn.f32x2 %0,%1,%2,%3;" : "=l"(d) : "l"(a), "l"(b), "l"(c)); return d; }
__device__ __forceinline__ float2 upk(u64 v) { float2 f; asm("mov.b64 {%0,%1},%2;" : "=f"(f.x), "=f"(f.y) : "l"(v)); return f; }

// ---------------- grouped 3x3 conv + lrelu -> split bf16 --------------------
__global__ void __launch_bounds__(256) gconv2_kernel(
    const float* __restrict__ in, const float* __restrict__ ke,
    bf16* __restrict__ oh, bf16* __restrict__ ol)
{
    __shared__ float sIn[16][18][34];
    __shared__ float sWt[16*9*16];
    const int tid = threadIdx.x;
    const int g = blockIdx.y, b = blockIdx.z;
    const int x0 = (blockIdx.x & 3)*32, y0 = (blockIdx.x >> 2)*16;
    const float* inb = in + ((size_t)(b*CC) + g*16)*HW;
    const float* kep = ke + (size_t)g*2304;

    for (int i = tid; i < 2304; i += 256) {
        int co = i/144, rem = i - co*144, ci = rem/9, t = rem - ci*9;
        sWt[(ci*9 + t)*16 + co] = kep[i];
    }
    for (int idx = tid; idx < 16*18*9; idx += 256) {
        int s = idx % 9, cr = idx / 9, c = cr/18, r = cr % 18, gy = y0 - 1 + r;
        bool yok = ((unsigned)gy < 128u);
        const float* row = inb + (size_t)c*HW + gy*WW;
        if (s < 8) {
            int j = 1 + 4*s;
            float4 v = yok ? *(const float4*)(row + x0 + 4*s) : make_float4(0,0,0,0);
            sIn[c][r][j]=v.x; sIn[c][r][j+1]=v.y; sIn[c][r][j+2]=v.z; sIn[c][r][j+3]=v.w;
        } else {
            sIn[c][r][0]  = (yok && x0-1 >= 0) ? row[x0-1] : 0.f;
            sIn[c][r][33] = (yok && x0+32 < 128) ? row[x0+32] : 0.f;
        }
    }
    __syncthreads();

    const int tx = tid & 31, ty = tid >> 5;
    u64 accA[8], accB[8];
    #pragma unroll
    for (int j = 0; j < 8; ++j) { accA[j]=0ull; accB[j]=0ull; }
    #pragma unroll 1
    for (int ci = 0; ci < 16; ++ci)
        #pragma unroll
        for (int kh = 0; kh < 3; ++kh) {
            u64 As[3] = { splat2(sIn[ci][ty+kh][tx]),   splat2(sIn[ci][ty+kh][tx+1]),   splat2(sIn[ci][ty+kh][tx+2]) };
            u64 Bs[3] = { splat2(sIn[ci][ty+8+kh][tx]), splat2(sIn[ci][ty+8+kh][tx+1]), splat2(sIn[ci][ty+8+kh][tx+2]) };
            const float* wb = &sWt[(ci*9 + kh*3)*16];
            #pragma unroll
            for (int kw = 0; kw < 3; ++kw) {
                const float* w = wb + kw*16;
                #pragma unroll
                for (int jp = 0; jp < 8; jp += 2) {
                    float4 w4 = *(const float4*)(w + 2*jp);
                    u64 wp0 = pk2(w4.x, w4.y), wp1 = pk2(w4.z, w4.w);
                    accA[jp]   = ffma2(As[kw], wp0, accA[jp]);
                    accA[jp+1] = ffma2(As[kw], wp1, accA[jp+1]);
                    accB[jp]   = ffma2(Bs[kw], wp0, accB[jp]);
                    accB[jp+1] = ffma2(Bs[kw], wp1, accB[jp+1]);
                }
            }
        }
    const int yA = y0 + ty, yB = y0 + ty + 8, x = x0 + tx;
    #pragma unroll
    for (int jp = 0; jp < 8; ++jp) {
        float2 a = upk(accA[jp]), bb = upk(accB[jp]);
        size_t c0 = ((size_t)(b*CC) + g*16 + 2*jp)*HW, c1 = c0 + HW;
        bf16 h,l;
        split1(lrelu(a.x),  h,l); oh[c0 + yA*WW + x] = h; ol[c0 + yA*WW + x] = l;
        split1(lrelu(a.y),  h,l); oh[c1 + yA*WW + x] = h; ol[c1 + yA*WW + x] = l;
        split1(lrelu(bb.x), h,l); oh[c0 + yB*WW + x] = h; ol[c0 + yB*WW + x] = l;
        split1(lrelu(bb.y), h,l); oh[c1 + yB*WW + x] = h; ol[c1 + yB*WW + x] = l;
    }
}

// ---------------- per-pixel dynamic local conv ------------------------------
template<bool RES, bool SPLIT>
__global__ void __launch_bounds__(256) localconv2_kernel(
    const float* __restrict__ in, const float* __restrict__ wb,
    const float* __restrict__ res, float* __restrict__ out,
    bf16* __restrict__ oh, bf16* __restrict__ ol)
{
    __shared__ float sh[8][10][34];
    const int tid = threadIdx.x, b = blockIdx.y;
    const int x0 = (blockIdx.x & 3)*32, y0 = (blockIdx.x >> 2)*8;
    const int tx = tid & 31, ty = tid >> 5;
    const int pix = (y0 + ty)*WW + x0 + tx;
    const float* inb = in + (size_t)b*CC*HW;
    const float* wbb = wb + (size_t)b*72*HW + pix;
    const float* rb  = RES ? res + (size_t)b*CC*HW + pix : nullptr;

    #pragma unroll 1
    for (int kg = 0; kg < 8; ++kg) {
        __syncthreads();
        const float* cb = inb + (size_t)kg*8*HW;
        for (int idx = tid; idx < 8*10*9; idx += 256) {
            int s = idx % 9, cr = idx / 9, c = cr/10, r = cr % 10, gy = y0 - 1 + r;
            bool yok = ((unsigned)gy < 128u);
            const float* row = cb + (size_t)c*HW + gy*WW;
            if (s < 8) {
                int j = 1 + 4*s;
                float4 v = yok ? *(const float4*)(row + x0 + 4*s) : make_float4(0,0,0,0);
                sh[c][r][j]=v.x; sh[c][r][j+1]=v.y; sh[c][r][j+2]=v.z; sh[c][r][j+3]=v.w;
            } else {
                sh[c][r][0]  = (yok && x0-1 >= 0) ? row[x0-1] : 0.f;
                sh[c][r][33] = (yok && x0+32 < 128) ? row[x0+32] : 0.f;
            }
        }
        __syncthreads();
        u64 ws[9];
        #pragma unroll
        for (int t = 0; t < 9; ++t) ws[t] = splat2(wbb[(size_t)(kg*9 + t)*HW]);
        #pragma unroll
        for (int cp = 0; cp < 4; ++cp) {
            const int c0 = 2*cp, ch = kg*8 + c0;
            u64 acc = RES ? pk2(rb[(size_t)ch*HW], rb[(size_t)(ch+1)*HW]) : 0ull;
            #pragma unroll
            for (int kh = 0; kh < 3; ++kh)
                #pragma unroll
                for (int kw = 0; kw < 3; ++kw)
                    acc = ffma2(pk2(sh[c0][ty+kh][tx+kw], sh[c0+1][ty+kh][tx+kw]), ws[kh*3+kw], acc);
            float2 r = upk(acc);
            size_t o0 = (size_t)(b*CC + ch)*HW + pix, o1 = o0 + HW;
            if (SPLIT) {
                bf16 h,l;
                split1(r.x,h,l); oh[o0]=h; ol[o0]=l;
                split1(r.y,h,l); oh[o1]=h; ol[o1]=l;
            } else { out[o0] = r.x; out[o1] = r.y; }
        }
    }
}

// ---------------- softmax over H --------------------------------------------
__global__ void __launch_bounds__(128) softmax_h(float* __restrict__ a)
{
    const int ch = blockIdx.x, b = blockIdx.y;
    float* col = a + ((size_t)(b*72) + ch)*HW + threadIdx.x;
    float m = -1e30f;
    #pragma unroll 4
    for (int h = 0; h < 128; ++h) m = fmaxf(m, col[h*WW]);
    float s = 0.f;
    #pragma unroll 4
    for (int h = 0; h < 128; ++h) s += __expf(col[h*WW] - m);
    float inv = 1.f / s;
    #pragma unroll 4
    for (int h = 0; h < 128; ++h) col[h*WW] = __expf(col[h*WW] - m) * inv;
}

// ---------------- launch ----------------------------------------------------
extern "C" void kernel_launch(void* const* d_in, const int* in_sizes, int n_in,
                              void* d_out, int out_size)
{
    (void)in_sizes; (void)n_in; (void)out_size;
    const float* x     = (const float*)d_in[0];
    const float* phi_w = (const float*)d_in[1];
    const float* phi_b = (const float*)d_in[2];
    const float* th_w  = (const float*)d_in[3];
    const float* th_b  = (const float*)d_in[4];
    const float* ke_w  = (const float*)d_in[5];
    const float* e1_w  = (const float*)d_in[6];
    const float* e2_w  = (const float*)d_in[7];
    const float* e2_b  = (const float*)d_in[8];
    const float* c1_w  = (const float*)d_in[9];
    const float* sw1_w = (const float*)d_in[10];
    const float* sw2_w = (const float*)d_in[11];
    const float* sw2_b = (const float*)d_in[12];
    const float* sec_w = (const float*)d_in[13];
    const float* sec_b = (const float*)d_in[14];

    float *key0, *h0, *gg, *w72, *attn;
    bf16 *xh,*xl,*qh,*ql,*kh,*kl,*hh,*hl,*mh,*ml;
    cudaGetSymbolAddress((void**)&key0, g_key0);
    cudaGetSymbolAddress((void**)&h0,   g_h0);
    cudaGetSymbolAddress((void**)&gg,   g_gg);
    cudaGetSymbolAddress((void**)&w72,  g_w72);
    cudaGetSymbolAddress((void**)&attn, g_attn);
    cudaGetSymbolAddress((void**)&xh, g_xh); cudaGetSymbolAddress((void**)&xl, g_xl);
    cudaGetSymbolAddress((void**)&qh, g_qh); cudaGetSymbolAddress((void**)&ql, g_ql);
    cudaGetSymbolAddress((void**)&kh, g_kh); cudaGetSymbolAddress((void**)&kl, g_kl);
    cudaGetSymbolAddress((void**)&hh, g_hh); cudaGetSymbolAddress((void**)&hl, g_hl);
    cudaGetSymbolAddress((void**)&mh, g_mh); cudaGetSymbolAddress((void**)&ml, g_ml);

    // smem sizes: (2*128*CINP2 + 2*COP*CINP2)*4 + COP*4
    constexpr int SM_64   = (2*128*36 + 2*64*36)*4 + 64*4;    // 55552
    constexpr int SM_E1   = (2*128*68 + 2*32*68)*4 + 32*4;    // 87168
    constexpr int SM_E2   = (2*128*20 + 2*80*20)*4 + 80*4;    // 33600
    constexpr int SM_SEC  = (2*128*68 + 2*64*68)*4 + 64*4;    // 104704

    cudaFuncSetAttribute(pw_hmma<64,0,64,4,8,false,false>,  cudaFuncAttributeMaxDynamicSharedMemorySize, SM_64);
    cudaFuncSetAttribute(pw_hmma<64,0,64,4,8,false,true>,   cudaFuncAttributeMaxDynamicSharedMemorySize, SM_64);
    cudaFuncSetAttribute(pw_hmma<64,64,32,2,4,true,true>,   cudaFuncAttributeMaxDynamicSharedMemorySize, SM_E1);
    cudaFuncSetAttribute(pw_hmma<32,0,72,5,10,false,false>, cudaFuncAttributeMaxDynamicSharedMemorySize, SM_E2);
    cudaFuncSetAttribute(pw_hmma<64,64,64,4,8,false,false>, cudaFuncAttributeMaxDynamicSharedMemorySize, SM_SEC);

    dim3 pg(128, BATCH);

    prep_x<<<4096, 512>>>(x, xh, xl);

    // key0 = phi(x); query = theta(x) [split]; h0 = c1(x)
    pw_hmma<64,0,64,4,8,false,false><<<pg,256,SM_64>>>(xh,xl,nullptr,nullptr, phi_w, phi_b, key0, nullptr,nullptr);
    pw_hmma<64,0,64,4,8,false,true ><<<pg,256,SM_64>>>(xh,xl,nullptr,nullptr, th_w,  th_b,  nullptr, qh, ql);
    pw_hmma<64,0,64,4,8,false,false><<<pg,256,SM_64>>>(xh,xl,nullptr,nullptr, c1_w,  nullptr, h0, nullptr,nullptr);

    // key = lrelu(gconv(key0)) [split]
    gconv2_kernel<<<dim3(32,4,BATCH),256>>>(key0, ke_w, kh, kl);

    // mid = lrelu(e1([q,k])) [split]; w72 = e2(mid)
    pw_hmma<64,64,32,2,4,true,true ><<<pg,128,SM_E1>>>(qh,ql, kh,kl, e1_w, nullptr, nullptr, mh, ml);
    pw_hmma<32,0,72,5,10,false,false><<<pg,320,SM_E2>>>(mh,ml, nullptr,nullptr, e2_w, e2_b, w72, nullptr,nullptr);

    // h1 = local_conv(h0, w72) [split]
    localconv2_kernel<false,true><<<dim3(64,BATCH),256>>>(h0, w72, nullptr, nullptr, hh, hl);

    // attn = softmax_H(sw2(lrelu(sw1([h1,k]))))
    pw_hmma<64,64,32,2,4,true,true ><<<pg,128,SM_E1>>>(hh,hl, kh,kl, sw1_w, nullptr, nullptr, mh, ml);
    pw_hmma<32,0,72,5,10,false,false><<<pg,320,SM_E2>>>(mh,ml, nullptr,nullptr, sw2_w, sw2_b, attn, nullptr,nullptr);
    softmax_h<<<dim3(72,BATCH),128>>>(attn);

    // out = local_conv(sec([h1,k]), attn) + x
    pw_hmma<64,64,64,4,8,false,false><<<pg,256,SM_SEC>>>(hh,hl, kh,kl, sec_w, sec_b, gg, nullptr,nullptr);
    localconv2_kernel<true,false><<<dim3(64,BATCH),256>>>(gg, attn, x, (float*)d_out, nullptr,nullptr);
}

// round 10
// speedup vs baseline: 1.3910x; 1.0699x over previous
#include <cuda_runtime.h>
#include <cuda_bf16.h>
#include <cstdint>

#define BATCH 8
#define CC    64
#define WW    128
#define HW    16384
typedef unsigned long long u64;
typedef unsigned int u32;
typedef unsigned short u16;
typedef __nv_bfloat16 bf16;

// ---------------- helpers ---------------------------------------------------
__device__ __forceinline__ u32 smem_u32(const void* p) {
    u32 a; asm("{ .reg .u64 t; cvta.to.shared.u64 t, %1; cvt.u32.u64 %0, t; }" : "=r"(a) : "l"(p)); return a;
}
__device__ __forceinline__ float lrelu(float v) { return fmaxf(v, 0.1f*v); }
__device__ __forceinline__ void split1(float v, bf16& h, bf16& l) {
    h = __float2bfloat16(v); l = __float2bfloat16(v - __bfloat162float(h));
}
__device__ __forceinline__ void split2(float a, float b, u32& h, u32& l) {
    bf16 ah,al,bh,bl; split1(a,ah,al); split1(b,bh,bl);
    __nv_bfloat162 H = __halves2bfloat162(ah,bh), L = __halves2bfloat162(al,bl);
    h = *(u32*)&H; l = *(u32*)&L;
}

#define LDMX4(r, addr) asm volatile( \
    "ldmatrix.sync.aligned.m8n8.x4.shared.b16 {%0,%1,%2,%3}, [%4];" \
    : "=r"((r)[0]),"=r"((r)[1]),"=r"((r)[2]),"=r"((r)[3]) : "r"(addr))

#define MMA16(d, a, b0, b1) asm volatile( \
    "mma.sync.aligned.m16n8k16.row.col.f32.bf16.bf16.f32 " \
    "{%0,%1,%2,%3},{%4,%5,%6,%7},{%8,%9},{%0,%1,%2,%3};" \
    : "+f"((d)[0]),"+f"((d)[1]),"+f"((d)[2]),"+f"((d)[3]) \
    : "r"((a)[0]),"r"((a)[1]),"r"((a)[2]),"r"((a)[3]), "r"(b0),"r"(b1))

// ---------------- scratch ---------------------------------------------------
__device__ float g_key0[BATCH*CC*HW];
__device__ float g_h0  [BATCH*CC*HW];
__device__ float g_gg  [BATCH*CC*HW];
__device__ float g_w72 [BATCH*72*HW];
__device__ float g_attn[BATCH*72*HW];
__device__ bf16 g_xh[BATCH*CC*HW],  g_xl[BATCH*CC*HW];
__device__ bf16 g_qh[BATCH*CC*HW],  g_ql[BATCH*CC*HW];
__device__ bf16 g_kh[BATCH*CC*HW],  g_kl[BATCH*CC*HW];
__device__ bf16 g_hh[BATCH*CC*HW],  g_hl[BATCH*CC*HW];

// ---------------- prep: x -> bf16 hi/lo -------------------------------------
__global__ void __launch_bounds__(512) prep_x(const float* __restrict__ x,
                                              bf16* __restrict__ xh, bf16* __restrict__ xl)
{
    int i = blockIdx.x*512 + threadIdx.x;
    float4 v = reinterpret_cast<const float4*>(x)[i];
    u32 h0,l0,h1,l1; split2(v.x,v.y,h0,l0); split2(v.z,v.w,h1,l1);
    reinterpret_cast<uint2*>(xh)[i] = make_uint2(h0,h1);
    reinterpret_cast<uint2*>(xl)[i] = make_uint2(l0,l1);
}

// ---------------- X staging helper (transpose ch-major -> [px][cinpair]) ----
template<int C1, int C2, int CINP2, int NWARP>
__device__ __forceinline__ void stage_x(
    u32* XH, u32* XL, const bf16* p1h, const bf16* p1l,
    const bf16* p2h, const bf16* p2l, int b, int pxb, int lane, int wid)
{
    constexpr int KP2 = (C1 + C2)/2;
    for (int chunk = wid; chunk < 16; chunk += NWARP) {
        for (int cp = lane; cp < KP2; cp += 32) {
            int ch = 2*cp;
            const bf16 *ph, *pl;
            if (ch < C1) { size_t o = ((size_t)b*C1 + ch)*HW + pxb + chunk*8; ph = p1h + o; pl = p1l + o; }
            else         { size_t o = ((size_t)b*C2 + (ch-C1))*HW + pxb + chunk*8; ph = p2h + o; pl = p2l + o; }
            uint4 a0 = *(const uint4*)ph, a1 = *(const uint4*)(ph + HW);
            uint4 c0 = *(const uint4*)pl, c1 = *(const uint4*)(pl + HW);
            u32* dh = &XH[(chunk*8)*CINP2 + cp];
            u32* dl = &XL[(chunk*8)*CINP2 + cp];
            dh[0*CINP2] = __byte_perm(a0.x, a1.x, 0x5410); dh[1*CINP2] = __byte_perm(a0.x, a1.x, 0x7632);
            dh[2*CINP2] = __byte_perm(a0.y, a1.y, 0x5410); dh[3*CINP2] = __byte_perm(a0.y, a1.y, 0x7632);
            dh[4*CINP2] = __byte_perm(a0.z, a1.z, 0x5410); dh[5*CINP2] = __byte_perm(a0.z, a1.z, 0x7632);
            dh[6*CINP2] = __byte_perm(a0.w, a1.w, 0x5410); dh[7*CINP2] = __byte_perm(a0.w, a1.w, 0x7632);
            dl[0*CINP2] = __byte_perm(c0.x, c1.x, 0x5410); dl[1*CINP2] = __byte_perm(c0.x, c1.x, 0x7632);
            dl[2*CINP2] = __byte_perm(c0.y, c1.y, 0x5410); dl[3*CINP2] = __byte_perm(c0.y, c1.y, 0x7632);
            dl[4*CINP2] = __byte_perm(c0.z, c1.z, 0x5410); dl[5*CINP2] = __byte_perm(c0.z, c1.z, 0x7632);
            dl[6*CINP2] = __byte_perm(c0.w, c1.w, 0x5410); dl[7*CINP2] = __byte_perm(c0.w, c1.w, 0x7632);
        }
    }
}

// ---------------- pw3: phi/theta/c1 share one X staging ---------------------
// CIN=64, three 64-row weight images. 256 thr, 128 px per block.
__global__ void __launch_bounds__(256, 1) pw3_kernel(
    const bf16* __restrict__ xh, const bf16* __restrict__ xl,
    const float* __restrict__ phi_w, const float* __restrict__ phi_b,
    const float* __restrict__ th_w,  const float* __restrict__ th_b,
    const float* __restrict__ c1_w,
    float* __restrict__ key0, bf16* __restrict__ qh, bf16* __restrict__ ql,
    float* __restrict__ h0)
{
    constexpr int CINP2 = 36, WIMG = 64*36;
    extern __shared__ u32 sm[];
    u32* XH = sm;                 // 128*36
    u32* XL = XH + 128*36;
    u32* WB = XL + 128*36;        // 3 images x (hi|lo) x 64*36
    float* SB = (float*)(WB + 6*WIMG);   // 192

    const int tid = threadIdx.x, lane = tid & 31, wid = tid >> 5;
    const int b = blockIdx.y, pxb = blockIdx.x * 128;

    stage_x<64,0,CINP2,8>(XH, XL, xh, xl, nullptr, nullptr, b, pxb, lane, wid);

    #pragma unroll
    for (int img = 0; img < 3; ++img) {
        const float* Wt = (img == 0) ? phi_w : (img == 1) ? th_w : c1_w;
        u32* WH = WB + img*2*WIMG;
        u32* WL = WH + WIMG;
        for (int i = tid; i < 64*32; i += 256) {
            int co = i >> 5, cp = i & 31;
            float2 wv = *(const float2*)(Wt + (size_t)co*64 + 2*cp);
            u32 H, L; split2(wv.x, wv.y, H, L);
            WH[co*CINP2 + cp] = H; WL[co*CINP2 + cp] = L;
        }
    }
    if (tid < 192) {
        int img = tid >> 6, co = tid & 63;
        SB[tid] = (img == 0) ? phi_b[co] : (img == 1) ? th_b[co] : 0.f;
    }
    __syncthreads();

    const int mt = wid % 4, nh = wid / 4;
    const int co0 = mt*16, pn0 = nh*64;
    const int arow = co0 + (lane & 7) + ((lane >> 3) & 1)*8;
    const int acw  = ((lane >> 4) & 1)*4;
    const int brow = pn0 + (lane >> 2), bcol = lane & 3;
    const u32* bXH = &XH[brow*CINP2 + bcol];
    const u32* bXL = &XL[brow*CINP2 + bcol];
    const int g = lane >> 2, c = lane & 3;
    const int coA = co0 + g, coB = coA + 8;

    #pragma unroll
    for (int img = 0; img < 3; ++img) {
        const u32 aBH = smem_u32(WB + img*2*WIMG) + (arow*CINP2 + acw)*4;
        const u32 aBL = aBH + WIMG*4;
        float acc[8][4];
        #pragma unroll
        for (int n = 0; n < 8; ++n) { acc[n][0]=0.f; acc[n][1]=0.f; acc[n][2]=0.f; acc[n][3]=0.f; }
        #pragma unroll
        for (int ks = 0; ks < 4; ++ks) {
            u32 Ah[4], Al[4];
            LDMX4(Ah, aBH + ks*32);
            LDMX4(Al, aBL + ks*32);
            #pragma unroll
            for (int nt = 0; nt < 8; ++nt) {
                u32 bh0 = bXH[nt*8*CINP2 + ks*8], bh1 = bXH[nt*8*CINP2 + ks*8 + 4];
                u32 bl0 = bXL[nt*8*CINP2 + ks*8], bl1 = bXL[nt*8*CINP2 + ks*8 + 4];
                MMA16(acc[nt], Ah, bh0, bh1);
                MMA16(acc[nt], Ah, bl0, bl1);
                MMA16(acc[nt], Al, bh0, bh1);
            }
        }
        const float bvA = SB[img*64 + coA], bvB = SB[img*64 + coB];
        #pragma unroll
        for (int nt = 0; nt < 8; ++nt) {
            int px = pxb + pn0 + nt*8 + 2*c;
            float v0 = acc[nt][0] + bvA, v1 = acc[nt][1] + bvA;
            float v2 = acc[nt][2] + bvB, v3 = acc[nt][3] + bvB;
            size_t oA = ((size_t)b*64 + coA)*HW + px;
            size_t oB = ((size_t)b*64 + coB)*HW + px;
            if (img == 0) {
                *(float2*)(key0 + oA) = make_float2(v0,v1);
                *(float2*)(key0 + oB) = make_float2(v2,v3);
            } else if (img == 1) {
                u32 H,L; split2(v0,v1,H,L);
                *(u32*)(qh + oA) = H; *(u32*)(ql + oA) = L;
                split2(v2,v3,H,L);
                *(u32*)(qh + oB) = H; *(u32*)(ql + oB) = L;
            } else {
                *(float2*)(h0 + oA) = make_float2(v0,v1);
                *(float2*)(h0 + oB) = make_float2(v2,v3);
            }
        }
    }
}

// ---------------- fused e1+e2 (and sw1+sw2) ---------------------------------
// GEMM1: mid[32,128px] = lrelu(W1[32,128] x [in1;in2]) -> split bf16 in smem
// GEMM2: out[72,128px] = W2[72,32] x mid + bias
__global__ void __launch_bounds__(256, 1) fused_e_kernel(
    const bf16* __restrict__ p1h, const bf16* __restrict__ p1l,
    const bf16* __restrict__ p2h, const bf16* __restrict__ p2l,
    const float* __restrict__ W1t, const float* __restrict__ W2t,
    const float* __restrict__ bias2, float* __restrict__ of)
{
    constexpr int CINP2 = 68, C2P2 = 20;
    extern __shared__ u32 sm[];
    u32* XH  = sm;                  // 128*68
    u32* XL  = XH + 128*68;
    u32* W1H = XL + 128*68;         // 32*68
    u32* W1L = W1H + 32*68;
    u32* W2H = W1L + 32*68;         // 80*20
    u32* W2L = W2H + 80*20;
    u32* X2H = W2L + 80*20;         // 128*20
    u32* X2L = X2H + 128*20;
    float* SB = (float*)(X2L + 128*20);  // 80

    const int tid = threadIdx.x, lane = tid & 31, wid = tid >> 5;
    const int b = blockIdx.y, pxb = blockIdx.x * 128;

    stage_x<64,64,CINP2,8>(XH, XL, p1h, p1l, p2h, p2l, b, pxb, lane, wid);

    for (int i = tid; i < 32*64; i += 256) {
        int co = i >> 6, cp = i & 63;
        float2 wv = *(const float2*)(W1t + (size_t)co*128 + 2*cp);
        u32 H, L; split2(wv.x, wv.y, H, L);
        W1H[co*CINP2 + cp] = H; W1L[co*CINP2 + cp] = L;
    }
    for (int i = tid; i < 80*16; i += 256) {
        int co = i >> 4, cp = i & 15;
        float2 wv = make_float2(0.f, 0.f);
        if (co < 72) wv = *(const float2*)(W2t + (size_t)co*32 + 2*cp);
        u32 H, L; split2(wv.x, wv.y, H, L);
        W2H[co*C2P2 + cp] = H; W2L[co*C2P2 + cp] = L;
    }
    if (tid < 80) SB[tid] = (tid < 72) ? bias2[tid] : 0.f;
    __syncthreads();

    // ---- GEMM1: 32 rows x 128 px, 8 warps (2 M-tiles x 4 N-tiles of 32px) --
    {
        const int mt = wid & 1, nh = wid >> 1;
        const int co0 = mt*16, pn0 = nh*32;
        const int arow = co0 + (lane & 7) + ((lane >> 3) & 1)*8;
        const int acw  = ((lane >> 4) & 1)*4;
        const u32 aBH = smem_u32(&W1H[arow*CINP2 + acw]);
        const u32 aBL = smem_u32(&W1L[arow*CINP2 + acw]);
        const int brow = pn0 + (lane >> 2), bcol = lane & 3;
        const u32* bXH = &XH[brow*CINP2 + bcol];
        const u32* bXL = &XL[brow*CINP2 + bcol];
        float acc[4][4];
        #pragma unroll
        for (int n = 0; n < 4; ++n) { acc[n][0]=0.f; acc[n][1]=0.f; acc[n][2]=0.f; acc[n][3]=0.f; }
        #pragma unroll
        for (int ks = 0; ks < 8; ++ks) {
            u32 Ah[4], Al[4];
            LDMX4(Ah, aBH + ks*32);
            LDMX4(Al, aBL + ks*32);
            #pragma unroll
            for (int nt = 0; nt < 4; ++nt) {
                u32 bh0 = bXH[nt*8*CINP2 + ks*8], bh1 = bXH[nt*8*CINP2 + ks*8 + 4];
                u32 bl0 = bXL[nt*8*CINP2 + ks*8], bl1 = bXL[nt*8*CINP2 + ks*8 + 4];
                MMA16(acc[nt], Ah, bh0, bh1);
                MMA16(acc[nt], Ah, bl0, bl1);
                MMA16(acc[nt], Al, bh0, bh1);
            }
        }
        // epilogue -> X2 (u16 halves; word ch>>1, half ch&1 => u16 index px*40+ch)
        const int g = lane >> 2, c = lane & 3;
        const int coA = co0 + g, coB = coA + 8;
        bf16* x2h = (bf16*)X2H; bf16* x2l = (bf16*)X2L;
        #pragma unroll
        for (int nt = 0; nt < 4; ++nt) {
            int px = pn0 + nt*8 + 2*c;
            float v0 = lrelu(acc[nt][0]), v1 = lrelu(acc[nt][1]);
            float v2 = lrelu(acc[nt][2]), v3 = lrelu(acc[nt][3]);
            bf16 h, l;
            split1(v0, h, l); x2h[(px  )*40 + coA] = h; x2l[(px  )*40 + coA] = l;
            split1(v1, h, l); x2h[(px+1)*40 + coA] = h; x2l[(px+1)*40 + coA] = l;
            split1(v2, h, l); x2h[(px  )*40 + coB] = h; x2l[(px  )*40 + coB] = l;
            split1(v3, h, l); x2h[(px+1)*40 + coB] = h; x2l[(px+1)*40 + coB] = l;
        }
    }
    __syncthreads();

    // ---- GEMM2: 72 rows x 128 px ----
    const int bcol = lane & 3;
    const int g = lane >> 2, c = lane & 3;
    // pass 1: rows 0-63, all 8 warps
    {
        const int mt = wid % 4, nh = wid / 4;
        const int co0 = mt*16, pn0 = nh*64;
        const int arow = co0 + (lane & 7) + ((lane >> 3) & 1)*8;
        const int acw  = ((lane >> 4) & 1)*4;
        const u32 aBH = smem_u32(&W2H[arow*C2P2 + acw]);
        const u32 aBL = smem_u32(&W2L[arow*C2P2 + acw]);
        const int brow = pn0 + (lane >> 2);
        const u32* bXH = &X2H[brow*C2P2 + bcol];
        const u32* bXL = &X2L[brow*C2P2 + bcol];
        float acc[8][4];
        #pragma unroll
        for (int n = 0; n < 8; ++n) { acc[n][0]=0.f; acc[n][1]=0.f; acc[n][2]=0.f; acc[n][3]=0.f; }
        #pragma unroll
        for (int ks = 0; ks < 2; ++ks) {
            u32 Ah[4], Al[4];
            LDMX4(Ah, aBH + ks*32);
            LDMX4(Al, aBL + ks*32);
            #pragma unroll
            for (int nt = 0; nt < 8; ++nt) {
                u32 bh0 = bXH[nt*8*C2P2 + ks*8], bh1 = bXH[nt*8*C2P2 + ks*8 + 4];
                u32 bl0 = bXL[nt*8*C2P2 + ks*8], bl1 = bXL[nt*8*C2P2 + ks*8 + 4];
                MMA16(acc[nt], Ah, bh0, bh1);
                MMA16(acc[nt], Ah, bl0, bl1);
                MMA16(acc[nt], Al, bh0, bh1);
            }
        }
        const int coA = co0 + g, coB = coA + 8;
        const float bvA = SB[coA], bvB = SB[coB];
        #pragma unroll
        for (int nt = 0; nt < 8; ++nt) {
            int px = pxb + pn0 + nt*8 + 2*c;
            *(float2*)(of + ((size_t)b*72 + coA)*HW + px) = make_float2(acc[nt][0]+bvA, acc[nt][1]+bvA);
            *(float2*)(of + ((size_t)b*72 + coB)*HW + px) = make_float2(acc[nt][2]+bvB, acc[nt][3]+bvB);
        }
    }
    // pass 2: rows 64-71, warps 0-1 (coB rows 72-79 are padding, skipped)
    if (wid < 2) {
        const int pn0 = wid*64;
        const int arow = 64 + (lane & 7) + ((lane >> 3) & 1)*8;
        const int acw  = ((lane >> 4) & 1)*4;
        const u32 aBH = smem_u32(&W2H[arow*C2P2 + acw]);
        const u32 aBL = smem_u32(&W2L[arow*C2P2 + acw]);
        const int brow = pn0 + (lane >> 2);
        const u32* bXH = &X2H[brow*C2P2 + bcol];
        const u32* bXL = &X2L[brow*C2P2 + bcol];
        float acc[8][4];
        #pragma unroll
        for (int n = 0; n < 8; ++n) { acc[n][0]=0.f; acc[n][1]=0.f; acc[n][2]=0.f; acc[n][3]=0.f; }
        #pragma unroll
        for (int ks = 0; ks < 2; ++ks) {
            u32 Ah[4], Al[4];
            LDMX4(Ah, aBH + ks*32);
            LDMX4(Al, aBL + ks*32);
            #pragma unroll
            for (int nt = 0; nt < 8; ++nt) {
                u32 bh0 = bXH[nt*8*C2P2 + ks*8], bh1 = bXH[nt*8*C2P2 + ks*8 + 4];
                u32 bl0 = bXL[nt*8*C2P2 + ks*8], bl1 = bXL[nt*8*C2P2 + ks*8 + 4];
                MMA16(acc[nt], Ah, bh0, bh1);
                MMA16(acc[nt], Ah, bl0, bl1);
                MMA16(acc[nt], Al, bh0, bh1);
            }
        }
        const int coA = 64 + g;   // 64..71, always valid; coB = 72..79 skipped
        const float bvA = SB[coA];
        #pragma unroll
        for (int nt = 0; nt < 8; ++nt) {
            int px = pxb + pn0 + nt*8 + 2*c;
            *(float2*)(of + ((size_t)b*72 + coA)*HW + px) = make_float2(acc[nt][0]+bvA, acc[nt][1]+bvA);
        }
    }
}

// ---------------- HMMA pointwise GEMM (sec only) -----------------------------
template<int C1, int C2, int COUT, int MT, int NWARP, bool LRELU, bool SPLIT>
__global__ void __launch_bounds__(NWARP*32, 1) pw_hmma(
    const bf16* __restrict__ p1h, const bf16* __restrict__ p1l,
    const bf16* __restrict__ p2h, const bf16* __restrict__ p2l,
    const float* __restrict__ Wt, const float* __restrict__ bias,
    float* __restrict__ of, bf16* __restrict__ oh, bf16* __restrict__ ol)
{
    constexpr int CIN = C1 + C2, KP2 = CIN/2;
    constexpr int CINP2 = (CIN == 128) ? 68 : (CIN == 64) ? 36 : 20;
    constexpr int COP = MT*16, NTH = NWARP*32, KS = CIN/16;

    extern __shared__ u32 sm[];
    u32* XH = sm;
    u32* XL = XH + 128*CINP2;
    u32* WH = XL + 128*CINP2;
    u32* WL = WH + COP*CINP2;
    float* SB = (float*)(WL + COP*CINP2);

    const int tid = threadIdx.x, lane = tid & 31, wid = tid >> 5;
    const int b = blockIdx.y, pxb = blockIdx.x * 128;

    stage_x<C1,C2,CINP2,NWARP>(XH, XL, p1h, p1l, p2h, p2l, b, pxb, lane, wid);

    for (int i = tid; i < COP*KP2; i += NTH) {
        int co = i / KP2, cp = i - co*KP2;
        float2 wv = make_float2(0.f, 0.f);
        if (co < COUT) wv = *(const float2*)(Wt + (size_t)co*CIN + 2*cp);
        u32 H, L; split2(wv.x, wv.y, H, L);
        WH[co*CINP2 + cp] = H; WL[co*CINP2 + cp] = L;
    }
    if (tid < COP) SB[tid] = (bias && tid < COUT) ? bias[tid] : 0.f;
    __syncthreads();

    const int mt = wid % MT, nh = wid / MT;
    const int co0 = mt*16, pn0 = nh*64;
    float acc[8][4];
    #pragma unroll
    for (int n = 0; n < 8; ++n) { acc[n][0]=0.f; acc[n][1]=0.f; acc[n][2]=0.f; acc[n][3]=0.f; }

    const int arow = co0 + (lane & 7) + ((lane >> 3) & 1)*8;
    const int acw  = ((lane >> 4) & 1)*4;
    const u32 aBH = smem_u32(&WH[arow*CINP2 + acw]);
    const u32 aBL = smem_u32(&WL[arow*CINP2 + acw]);
    const int brow = pn0 + (lane >> 2), bcol = lane & 3;
    const u32* bXH = &XH[brow*CINP2 + bcol];
    const u32* bXL = &XL[brow*CINP2 + bcol];

    #pragma unroll
    for (int ks = 0; ks < KS; ++ks) {
        u32 Ah[4], Al[4];
        LDMX4(Ah, aBH + ks*32);
        LDMX4(Al, aBL + ks*32);
        #pragma unroll
        for (int nt = 0; nt < 8; ++nt) {
            u32 bh0 = bXH[nt*8*CINP2 + ks*8], bh1 = bXH[nt*8*CINP2 + ks*8 + 4];
            u32 bl0 = bXL[nt*8*CINP2 + ks*8], bl1 = bXL[nt*8*CINP2 + ks*8 + 4];
            MMA16(acc[nt], Ah, bh0, bh1);
            MMA16(acc[nt], Ah, bl0, bl1);
            MMA16(acc[nt], Al, bh0, bh1);
        }
    }

    const int g = lane >> 2, c = lane & 3;
    const int coA = co0 + g, coB = coA + 8;
    const float bvA = SB[coA], bvB = SB[coB];
    #pragma unroll
    for (int nt = 0; nt < 8; ++nt) {
        int px = pxb + pn0 + nt*8 + 2*c;
        float v0 = acc[nt][0] + bvA, v1 = acc[nt][1] + bvA;
        float v2 = acc[nt][2] + bvB, v3 = acc[nt][3] + bvB;
        if (LRELU) { v0=lrelu(v0); v1=lrelu(v1); v2=lrelu(v2); v3=lrelu(v3); }
        if (SPLIT) {
            if (coA < COUT) {
                u32 H,L; split2(v0,v1,H,L);
                size_t o = ((size_t)b*COUT + coA)*HW + px;
                *(u32*)(oh + o) = H; *(u32*)(ol + o) = L;
            }
            if (coB < COUT) {
                u32 H,L; split2(v2,v3,H,L);
                size_t o = ((size_t)b*COUT + coB)*HW + px;
                *(u32*)(oh + o) = H; *(u32*)(ol + o) = L;
            }
        } else {
            if (coA < COUT) *(float2*)(of + ((size_t)b*COUT + coA)*HW + px) = make_float2(v0,v1);
            if (coB < COUT) *(float2*)(of + ((size_t)b*COUT + coB)*HW + px) = make_float2(v2,v3);
        }
    }
}

// ---------------- FFMA2 helpers ----------------------------------------------
__device__ __forceinline__ u64 pk2(float a, float b) { u64 r; asm("mov.b64 %0,{%1,%2};" : "=l"(r) : "f"(a), "f"(b)); return r; }
__device__ __forceinline__ u64 splat2(float a) { u64 r; asm("mov.b64 %0,{%1,%1};" : "=l"(r) : "f"(a)); return r; }
__device__ __forceinline__ u64 ffma2(u64 a, u64 b, u64 c) { u64 d; asm("fma.rn.f32x2 %0,%1,%2,%3;" : "=l"(d) : "l"(a), "l"(b), "l"(c)); return d; }
__device__ __forceinline__ float2 upk(u64 v) { float2 f; asm("mov.b64 {%0,%1},%2;" : "=f"(f.x), "=f"(f.y) : "l"(v)); return f; }

// ---------------- grouped 3x3 conv + lrelu -> split bf16 --------------------
__global__ void __launch_bounds__(256) gconv2_kernel(
    const float* __restrict__ in, const float* __restrict__ ke,
    bf16* __restrict__ oh, bf16* __restrict__ ol)
{
    __shared__ float sIn[16][18][34];
    __shared__ float sWt[16*9*16];
    const int tid = threadIdx.x;
    const int g = blockIdx.y, b = blockIdx.z;
    const int x0 = (blockIdx.x & 3)*32, y0 = (blockIdx.x >> 2)*16;
    const float* inb = in + ((size_t)(b*CC) + g*16)*HW;
    const float* kep = ke + (size_t)g*2304;

    for (int i = tid; i < 2304; i += 256) {
        int co = i/144, rem = i - co*144, ci = rem/9, t = rem - ci*9;
        sWt[(ci*9 + t)*16 + co] = kep[i];
    }
    for (int idx = tid; idx < 16*18*9; idx += 256) {
        int s = idx % 9, cr = idx / 9, c = cr/18, r = cr % 18, gy = y0 - 1 + r;
        bool yok = ((unsigned)gy < 128u);
        const float* row = inb + (size_t)c*HW + gy*WW;
        if (s < 8) {
            int j = 1 + 4*s;
            float4 v = yok ? *(const float4*)(row + x0 + 4*s) : make_float4(0,0,0,0);
            sIn[c][r][j]=v.x; sIn[c][r][j+1]=v.y; sIn[c][r][j+2]=v.z; sIn[c][r][j+3]=v.w;
        } else {
            sIn[c][r][0]  = (yok && x0-1 >= 0) ? row[x0-1] : 0.f;
            sIn[c][r][33] = (yok && x0+32 < 128) ? row[x0+32] : 0.f;
        }
    }
    __syncthreads();

    const int tx = tid & 31, ty = tid >> 5;
    u64 accA[8], accB[8];
    #pragma unroll
    for (int j = 0; j < 8; ++j) { accA[j]=0ull; accB[j]=0ull; }
    #pragma unroll 1
    for (int ci = 0; ci < 16; ++ci)
        #pragma unroll
        for (int kh = 0; kh < 3; ++kh) {
            u64 As[3] = { splat2(sIn[ci][ty+kh][tx]),   splat2(sIn[ci][ty+kh][tx+1]),   splat2(sIn[ci][ty+kh][tx+2]) };
            u64 Bs[3] = { splat2(sIn[ci][ty+8+kh][tx]), splat2(sIn[ci][ty+8+kh][tx+1]), splat2(sIn[ci][ty+8+kh][tx+2]) };
            const float* wb = &sWt[(ci*9 + kh*3)*16];
            #pragma unroll
            for (int kw = 0; kw < 3; ++kw) {
                const float* w = wb + kw*16;
                #pragma unroll
                for (int jp = 0; jp < 8; jp += 2) {
                    float4 w4 = *(const float4*)(w + 2*jp);
                    u64 wp0 = pk2(w4.x, w4.y), wp1 = pk2(w4.z, w4.w);
                    accA[jp]   = ffma2(As[kw], wp0, accA[jp]);
                    accA[jp+1] = ffma2(As[kw], wp1, accA[jp+1]);
                    accB[jp]   = ffma2(Bs[kw], wp0, accB[jp]);
                    accB[jp+1] = ffma2(Bs[kw], wp1, accB[jp+1]);
                }
            }
        }
    const int yA = y0 + ty, yB = y0 + ty + 8, x = x0 + tx;
    #pragma unroll
    for (int jp = 0; jp < 8; ++jp) {
        float2 a = upk(accA[jp]), bb = upk(accB[jp]);
        size_t c0 = ((size_t)(b*CC) + g*16 + 2*jp)*HW, c1 = c0 + HW;
        bf16 h,l;
        split1(lrelu(a.x),  h,l); oh[c0 + yA*WW + x] = h; ol[c0 + yA*WW + x] = l;
        split1(lrelu(a.y),  h,l); oh[c1 + yA*WW + x] = h; ol[c1 + yA*WW + x] = l;
        split1(lrelu(bb.x), h,l); oh[c0 + yB*WW + x] = h; ol[c0 + yB*WW + x] = l;
        split1(lrelu(bb.y), h,l); oh[c1 + yB*WW + x] = h; ol[c1 + yB*WW + x] = l;
    }
}

// ---------------- per-pixel dynamic local conv ------------------------------
template<bool RES, bool SPLIT>
__global__ void __launch_bounds__(256) localconv2_kernel(
    const float* __restrict__ in, const float* __restrict__ wb,
    const float* __restrict__ res, float* __restrict__ out,
    bf16* __restrict__ oh, bf16* __restrict__ ol)
{
    __shared__ float sh[8][10][34];
    const int tid = threadIdx.x, b = blockIdx.y;
    const int x0 = (blockIdx.x & 3)*32, y0 = (blockIdx.x >> 2)*8;
    const int tx = tid & 31, ty = tid >> 5;
    const int pix = (y0 + ty)*WW + x0 + tx;
    const float* inb = in + (size_t)b*CC*HW;
    const float* wbb = wb + (size_t)b*72*HW + pix;
    const float* rb  = RES ? res + (size_t)b*CC*HW + pix : nullptr;

    #pragma unroll 1
    for (int kg = 0; kg < 8; ++kg) {
        __syncthreads();
        const float* cb = inb + (size_t)kg*8*HW;
        for (int idx = tid; idx < 8*10*9; idx += 256) {
            int s = idx % 9, cr = idx / 9, c = cr/10, r = cr % 10, gy = y0 - 1 + r;
            bool yok = ((unsigned)gy < 128u);
            const float* row = cb + (size_t)c*HW + gy*WW;
            if (s < 8) {
                int j = 1 + 4*s;
                float4 v = yok ? *(const float4*)(row + x0 + 4*s) : make_float4(0,0,0,0);
                sh[c][r][j]=v.x; sh[c][r][j+1]=v.y; sh[c][r][j+2]=v.z; sh[c][r][j+3]=v.w;
            } else {
                sh[c][r][0]  = (yok && x0-1 >= 0) ? row[x0-1] : 0.f;
                sh[c][r][33] = (yok && x0+32 < 128) ? row[x0+32] : 0.f;
            }
        }
        __syncthreads();
        u64 ws[9];
        #pragma unroll
        for (int t = 0; t < 9; ++t) ws[t] = splat2(wbb[(size_t)(kg*9 + t)*HW]);
        #pragma unroll
        for (int cp = 0; cp < 4; ++cp) {
            const int c0 = 2*cp, ch = kg*8 + c0;
            u64 acc = RES ? pk2(rb[(size_t)ch*HW], rb[(size_t)(ch+1)*HW]) : 0ull;
            #pragma unroll
            for (int kh = 0; kh < 3; ++kh)
                #pragma unroll
                for (int kw = 0; kw < 3; ++kw)
                    acc = ffma2(pk2(sh[c0][ty+kh][tx+kw], sh[c0+1][ty+kh][tx+kw]), ws[kh*3+kw], acc);
            float2 r = upk(acc);
            size_t o0 = (size_t)(b*CC + ch)*HW + pix, o1 = o0 + HW;
            if (SPLIT) {
                bf16 h,l;
                split1(r.x,h,l); oh[o0]=h; ol[o0]=l;
                split1(r.y,h,l); oh[o1]=h; ol[o1]=l;
            } else { out[o0] = r.x; out[o1] = r.y; }
        }
    }
}

// ---------------- softmax over H --------------------------------------------
__global__ void __launch_bounds__(128) softmax_h(float* __restrict__ a)
{
    const int ch = blockIdx.x, b = blockIdx.y;
    float* col = a + ((size_t)(b*72) + ch)*HW + threadIdx.x;
    float m = -1e30f;
    #pragma unroll 4
    for (int h = 0; h < 128; ++h) m = fmaxf(m, col[h*WW]);
    float s = 0.f;
    #pragma unroll 4
    for (int h = 0; h < 128; ++h) s += __expf(col[h*WW] - m);
    float inv = 1.f / s;
    #pragma unroll 4
    for (int h = 0; h < 128; ++h) col[h*WW] = __expf(col[h*WW] - m) * inv;
}

// ---------------- launch ----------------------------------------------------
extern "C" void kernel_launch(void* const* d_in, const int* in_sizes, int n_in,
                              void* d_out, int out_size)
{
    (void)in_sizes; (void)n_in; (void)out_size;
    const float* x     = (const float*)d_in[0];
    const float* phi_w = (const float*)d_in[1];
    const float* phi_b = (const float*)d_in[2];
    const float* th_w  = (const float*)d_in[3];
    const float* th_b  = (const float*)d_in[4];
    const float* ke_w  = (const float*)d_in[5];
    const float* e1_w  = (const float*)d_in[6];
    const float* e2_w  = (const float*)d_in[7];
    const float* e2_b  = (const float*)d_in[8];
    const float* c1_w  = (const float*)d_in[9];
    const float* sw1_w = (const float*)d_in[10];
    const float* sw2_w = (const float*)d_in[11];
    const float* sw2_b = (const float*)d_in[12];
    const float* sec_w = (const float*)d_in[13];
    const float* sec_b = (const float*)d_in[14];

    float *key0, *h0, *gg, *w72, *attn;
    bf16 *xh,*xl,*qh,*ql,*kh,*kl,*hh,*hl;
    cudaGetSymbolAddress((void**)&key0, g_key0);
    cudaGetSymbolAddress((void**)&h0,   g_h0);
    cudaGetSymbolAddress((void**)&gg,   g_gg);
    cudaGetSymbolAddress((void**)&w72,  g_w72);
    cudaGetSymbolAddress((void**)&attn, g_attn);
    cudaGetSymbolAddress((void**)&xh, g_xh); cudaGetSymbolAddress((void**)&xl, g_xl);
    cudaGetSymbolAddress((void**)&qh, g_qh); cudaGetSymbolAddress((void**)&ql, g_ql);
    cudaGetSymbolAddress((void**)&kh, g_kh); cudaGetSymbolAddress((void**)&kl, g_kl);
    cudaGetSymbolAddress((void**)&hh, g_hh); cudaGetSymbolAddress((void**)&hl, g_hl);

    constexpr int SM_PW3 = (2*128*36 + 6*64*36)*4 + 192*4;                        // 92928
    constexpr int SM_FE  = (2*128*68 + 2*32*68 + 2*80*20 + 2*128*20)*4 + 80*4;    // 120640
    constexpr int SM_SEC = (2*128*68 + 2*64*68)*4 + 64*4;                         // 104704

    cudaFuncSetAttribute(pw3_kernel,    cudaFuncAttributeMaxDynamicSharedMemorySize, SM_PW3);
    cudaFuncSetAttribute(fused_e_kernel,cudaFuncAttributeMaxDynamicSharedMemorySize, SM_FE);
    cudaFuncSetAttribute(pw_hmma<64,64,64,4,8,false,false>, cudaFuncAttributeMaxDynamicSharedMemorySize, SM_SEC);

    dim3 pg(128, BATCH);

    prep_x<<<4096, 512>>>(x, xh, xl);

    // key0 = phi(x); q = theta(x) [split]; h0 = c1(x)  -- one fused kernel
    pw3_kernel<<<pg,256,SM_PW3>>>(xh,xl, phi_w,phi_b, th_w,th_b, c1_w, key0, qh,ql, h0);

    // key = lrelu(gconv(key0)) [split]
    gconv2_kernel<<<dim3(32,4,BATCH),256>>>(key0, ke_w, kh, kl);

    // w72 = e2(lrelu(e1([q,k])))  -- fused
    fused_e_kernel<<<pg,256,SM_FE>>>(qh,ql, kh,kl, e1_w, e2_w, e2_b, w72);

    // h1 = local_conv(h0, w72) [split]
    localconv2_kernel<false,true><<<dim3(64,BATCH),256>>>(h0, w72, nullptr, nullptr, hh, hl);

    // attn = softmax_H(sw2(lrelu(sw1([h1,k]))))  -- fused + softmax
    fused_e_kernel<<<pg,256,SM_FE>>>(hh,hl, kh,kl, sw1_w, sw2_w, sw2_b, attn);
    softmax_h<<<dim3(72,BATCH),128>>>(attn);

    // out = local_conv(sec([h1,k]), attn) + x
    pw_hmma<64,64,64,4,8,false,false><<<pg,256,SM_SEC>>>(hh,hl, kh,kl, sec_w, sec_b, gg, nullptr,nullptr);
    localconv2_kernel<true,false><<<dim3(64,BATCH),256>>>(gg, attn, x, (float*)d_out, nullptr,nullptr);
}

// round 13
// speedup vs baseline: 1.4625x; 1.0513x over previous
#include <cuda_runtime.h>
#include <cuda_bf16.h>
#include <cstdint>

#define BATCH 8
#define CC    64
#define WW    128
#define HW    16384
typedef unsigned long long u64;
typedef unsigned int u32;
typedef __nv_bfloat16 bf16;

// ---------------- helpers ---------------------------------------------------
__device__ __forceinline__ u32 smem_u32(const void* p) {
    u32 a; asm("{ .reg .u64 t; cvta.to.shared.u64 t, %1; cvt.u32.u64 %0, t; }" : "=r"(a) : "l"(p)); return a;
}
__device__ __forceinline__ float lrelu(float v) { return fmaxf(v, 0.1f*v); }
__device__ __forceinline__ void split1(float v, bf16& h, bf16& l) {
    h = __float2bfloat16(v); l = __float2bfloat16(v - __bfloat162float(h));
}
__device__ __forceinline__ void split2(float a, float b, u32& h, u32& l) {
    bf16 ah,al,bh,bl; split1(a,ah,al); split1(b,bh,bl);
    __nv_bfloat162 H = __halves2bfloat162(ah,bh), L = __halves2bfloat162(al,bl);
    h = *(u32*)&H; l = *(u32*)&L;
}

#define LDMX4(r, addr) asm volatile( \
    "ldmatrix.sync.aligned.m8n8.x4.shared.b16 {%0,%1,%2,%3}, [%4];" \
    : "=r"((r)[0]),"=r"((r)[1]),"=r"((r)[2]),"=r"((r)[3]) : "r"(addr))

#define MMA16(d, a, b0, b1) asm volatile( \
    "mma.sync.aligned.m16n8k16.row.col.f32.bf16.bf16.f32 " \
    "{%0,%1,%2,%3},{%4,%5,%6,%7},{%8,%9},{%0,%1,%2,%3};" \
    : "+f"((d)[0]),"+f"((d)[1]),"+f"((d)[2]),"+f"((d)[3]) \
    : "r"((a)[0]),"r"((a)[1]),"r"((a)[2]),"r"((a)[3]), "r"(b0),"r"(b1))

// ---------------- scratch ---------------------------------------------------
__device__ float g_key0[BATCH*CC*HW];
__device__ float g_h0  [BATCH*CC*HW];
__device__ float g_gg  [BATCH*CC*HW];
__device__ float g_w72 [BATCH*72*HW];
__device__ float g_attn[BATCH*72*HW];
__device__ bf16 g_xh[BATCH*CC*HW],  g_xl[BATCH*CC*HW];
__device__ bf16 g_qh[BATCH*CC*HW],  g_ql[BATCH*CC*HW];
__device__ bf16 g_kh[BATCH*CC*HW],  g_kl[BATCH*CC*HW];
__device__ bf16 g_hh[BATCH*CC*HW],  g_hl[BATCH*CC*HW];

// ---------------- prep: x -> bf16 hi/lo -------------------------------------
__global__ void __launch_bounds__(512) prep_x(const float* __restrict__ x,
                                              bf16* __restrict__ xh, bf16* __restrict__ xl)
{
    int i = blockIdx.x*512 + threadIdx.x;
    float4 v = reinterpret_cast<const float4*>(x)[i];
    u32 h0,l0,h1,l1; split2(v.x,v.y,h0,l0); split2(v.z,v.w,h1,l1);
    reinterpret_cast<uint2*>(xh)[i] = make_uint2(h0,h1);
    reinterpret_cast<uint2*>(xl)[i] = make_uint2(l0,l1);
}

// ---------------- X staging helper (transpose ch-major -> [px][cinpair]) ----
template<int C1, int C2, int CINP2, int NWARP>
__device__ __forceinline__ void stage_x(
    u32* XH, u32* XL, const bf16* p1h, const bf16* p1l,
    const bf16* p2h, const bf16* p2l, int b, int pxb, int lane, int wid)
{
    constexpr int KP2 = (C1 + C2)/2;
    for (int chunk = wid; chunk < 16; chunk += NWARP) {
        for (int cp = lane; cp < KP2; cp += 32) {
            int ch = 2*cp;
            const bf16 *ph, *pl;
            if (ch < C1) { size_t o = ((size_t)b*C1 + ch)*HW + pxb + chunk*8; ph = p1h + o; pl = p1l + o; }
            else         { size_t o = ((size_t)b*C2 + (ch-C1))*HW + pxb + chunk*8; ph = p2h + o; pl = p2l + o; }
            uint4 a0 = *(const uint4*)ph, a1 = *(const uint4*)(ph + HW);
            uint4 c0 = *(const uint4*)pl, c1 = *(const uint4*)(pl + HW);
            u32* dh = &XH[(chunk*8)*CINP2 + cp];
            u32* dl = &XL[(chunk*8)*CINP2 + cp];
            dh[0*CINP2] = __byte_perm(a0.x, a1.x, 0x5410); dh[1*CINP2] = __byte_perm(a0.x, a1.x, 0x7632);
            dh[2*CINP2] = __byte_perm(a0.y, a1.y, 0x5410); dh[3*CINP2] = __byte_perm(a0.y, a1.y, 0x7632);
            dh[4*CINP2] = __byte_perm(a0.z, a1.z, 0x5410); dh[5*CINP2] = __byte_perm(a0.z, a1.z, 0x7632);
            dh[6*CINP2] = __byte_perm(a0.w, a1.w, 0x5410); dh[7*CINP2] = __byte_perm(a0.w, a1.w, 0x7632);
            dl[0*CINP2] = __byte_perm(c0.x, c1.x, 0x5410); dl[1*CINP2] = __byte_perm(c0.x, c1.x, 0x7632);
            dl[2*CINP2] = __byte_perm(c0.y, c1.y, 0x5410); dl[3*CINP2] = __byte_perm(c0.y, c1.y, 0x7632);
            dl[4*CINP2] = __byte_perm(c0.z, c1.z, 0x5410); dl[5*CINP2] = __byte_perm(c0.z, c1.z, 0x7632);
            dl[6*CINP2] = __byte_perm(c0.w, c1.w, 0x5410); dl[7*CINP2] = __byte_perm(c0.w, c1.w, 0x7632);
        }
    }
}

// ---------------- pw3: phi/theta/c1 share one X staging, 512 thr ------------
__global__ void __launch_bounds__(512, 1) pw3_kernel(
    const bf16* __restrict__ xh, const bf16* __restrict__ xl,
    const float* __restrict__ phi_w, const float* __restrict__ phi_b,
    const float* __restrict__ th_w,  const float* __restrict__ th_b,
    const float* __restrict__ c1_w,
    float* __restrict__ key0, bf16* __restrict__ qh, bf16* __restrict__ ql,
    float* __restrict__ h0)
{
    constexpr int CINP2 = 36, WIMG = 64*36;
    extern __shared__ u32 sm[];
    u32* XH = sm;
    u32* XL = XH + 128*36;
    u32* WB = XL + 128*36;
    float* SB = (float*)(WB + 6*WIMG);

    const int tid = threadIdx.x, lane = tid & 31, wid = tid >> 5;
    const int b = blockIdx.y, pxb = blockIdx.x * 128;

    stage_x<64,0,CINP2,16>(XH, XL, xh, xl, nullptr, nullptr, b, pxb, lane, wid);

    #pragma unroll
    for (int img = 0; img < 3; ++img) {
        const float* Wt = (img == 0) ? phi_w : (img == 1) ? th_w : c1_w;
        u32* WH = WB + img*2*WIMG;
        u32* WL = WH + WIMG;
        for (int i = tid; i < 64*32; i += 512) {
            int co = i >> 5, cp = i & 31;
            float2 wv = *(const float2*)(Wt + (size_t)co*64 + 2*cp);
            u32 H, L; split2(wv.x, wv.y, H, L);
            WH[co*CINP2 + cp] = H; WL[co*CINP2 + cp] = L;
        }
    }
    if (tid < 192) {
        int img = tid >> 6, co = tid & 63;
        SB[tid] = (img == 0) ? phi_b[co] : (img == 1) ? th_b[co] : 0.f;
    }
    __syncthreads();

    const int mt = wid % 4, nh = wid / 4;          // 4 M-tiles x 4 N-tiles(32px)
    const int co0 = mt*16, pn0 = nh*32;
    const int arow = co0 + (lane & 7) + ((lane >> 3) & 1)*8;
    const int acw  = ((lane >> 4) & 1)*4;
    const int brow = pn0 + (lane >> 2), bcol = lane & 3;
    const u32* bXH = &XH[brow*CINP2 + bcol];
    const u32* bXL = &XL[brow*CINP2 + bcol];
    const int g = lane >> 2, c = lane & 3;
    const int coA = co0 + g, coB = coA + 8;

    #pragma unroll
    for (int img = 0; img < 3; ++img) {
        const u32 aBH = smem_u32(WB + img*2*WIMG) + (arow*CINP2 + acw)*4;
        const u32 aBL = aBH + WIMG*4;
        float acc[4][4];
        #pragma unroll
        for (int n = 0; n < 4; ++n) { acc[n][0]=0.f; acc[n][1]=0.f; acc[n][2]=0.f; acc[n][3]=0.f; }
        #pragma unroll
        for (int ks = 0; ks < 4; ++ks) {
            u32 Ah[4], Al[4];
            LDMX4(Ah, aBH + ks*32);
            LDMX4(Al, aBL + ks*32);
            #pragma unroll
            for (int nt = 0; nt < 4; ++nt) {
                u32 bh0 = bXH[nt*8*CINP2 + ks*8], bh1 = bXH[nt*8*CINP2 + ks*8 + 4];
                u32 bl0 = bXL[nt*8*CINP2 + ks*8], bl1 = bXL[nt*8*CINP2 + ks*8 + 4];
                MMA16(acc[nt], Ah, bh0, bh1);
                MMA16(acc[nt], Ah, bl0, bl1);
                MMA16(acc[nt], Al, bh0, bh1);
            }
        }
        const float bvA = SB[img*64 + coA], bvB = SB[img*64 + coB];
        #pragma unroll
        for (int nt = 0; nt < 4; ++nt) {
            int px = pxb + pn0 + nt*8 + 2*c;
            float v0 = acc[nt][0] + bvA, v1 = acc[nt][1] + bvA;
            float v2 = acc[nt][2] + bvB, v3 = acc[nt][3] + bvB;
            size_t oA = ((size_t)b*64 + coA)*HW + px;
            size_t oB = ((size_t)b*64 + coB)*HW + px;
            if (img == 0) {
                *(float2*)(key0 + oA) = make_float2(v0,v1);
                *(float2*)(key0 + oB) = make_float2(v2,v3);
            } else if (img == 1) {
                u32 H,L; split2(v0,v1,H,L);
                *(u32*)(qh + oA) = H; *(u32*)(ql + oA) = L;
                split2(v2,v3,H,L);
                *(u32*)(qh + oB) = H; *(u32*)(ql + oB) = L;
            } else {
                *(float2*)(h0 + oA) = make_float2(v0,v1);
                *(float2*)(h0 + oB) = make_float2(v2,v3);
            }
        }
    }
}

// ---------------- fused e1+e2 (and sw1+sw2), 512 thr ------------------------
__global__ void __launch_bounds__(512, 1) fused_e_kernel(
    const bf16* __restrict__ p1h, const bf16* __restrict__ p1l,
    const bf16* __restrict__ p2h, const bf16* __restrict__ p2l,
    const float* __restrict__ W1t, const float* __restrict__ W2t,
    const float* __restrict__ bias2, float* __restrict__ of)
{
    constexpr int CINP2 = 68, C2P2 = 20;
    extern __shared__ u32 sm[];
    u32* XH  = sm;
    u32* XL  = XH + 128*68;
    u32* W1H = XL + 128*68;
    u32* W1L = W1H + 32*68;
    u32* W2H = W1L + 32*68;
    u32* W2L = W2H + 80*20;
    u32* X2H = W2L + 80*20;
    u32* X2L = X2H + 128*20;
    float* SB = (float*)(X2L + 128*20);

    const int tid = threadIdx.x, lane = tid & 31, wid = tid >> 5;
    const int b = blockIdx.y, pxb = blockIdx.x * 128;

    stage_x<64,64,CINP2,16>(XH, XL, p1h, p1l, p2h, p2l, b, pxb, lane, wid);

    for (int i = tid; i < 32*64; i += 512) {
        int co = i >> 6, cp = i & 63;
        float2 wv = *(const float2*)(W1t + (size_t)co*128 + 2*cp);
        u32 H, L; split2(wv.x, wv.y, H, L);
        W1H[co*CINP2 + cp] = H; W1L[co*CINP2 + cp] = L;
    }
    for (int i = tid; i < 80*16; i += 512) {
        int co = i >> 4, cp = i & 15;
        float2 wv = make_float2(0.f, 0.f);
        if (co < 72) wv = *(const float2*)(W2t + (size_t)co*32 + 2*cp);
        u32 H, L; split2(wv.x, wv.y, H, L);
        W2H[co*C2P2 + cp] = H; W2L[co*C2P2 + cp] = L;
    }
    if (tid < 80) SB[tid] = (tid < 72) ? bias2[tid] : 0.f;
    __syncthreads();

    // ---- GEMM1: 32 rows x 128 px, 16 warps (2 M x 8 N-tiles of 16px) ------
    {
        const int mt = wid & 1, nh = wid >> 1;
        const int co0 = mt*16, pn0 = nh*16;
        const int arow = co0 + (lane & 7) + ((lane >> 3) & 1)*8;
        const int acw  = ((lane >> 4) & 1)*4;
        const u32 aBH = smem_u32(&W1H[arow*CINP2 + acw]);
        const u32 aBL = smem_u32(&W1L[arow*CINP2 + acw]);
        const int brow = pn0 + (lane >> 2), bcol = lane & 3;
        const u32* bXH = &XH[brow*CINP2 + bcol];
        const u32* bXL = &XL[brow*CINP2 + bcol];
        float acc[2][4];
        #pragma unroll
        for (int n = 0; n < 2; ++n) { acc[n][0]=0.f; acc[n][1]=0.f; acc[n][2]=0.f; acc[n][3]=0.f; }
        #pragma unroll
        for (int ks = 0; ks < 8; ++ks) {
            u32 Ah[4], Al[4];
            LDMX4(Ah, aBH + ks*32);
            LDMX4(Al, aBL + ks*32);
            #pragma unroll
            for (int nt = 0; nt < 2; ++nt) {
                u32 bh0 = bXH[nt*8*CINP2 + ks*8], bh1 = bXH[nt*8*CINP2 + ks*8 + 4];
                u32 bl0 = bXL[nt*8*CINP2 + ks*8], bl1 = bXL[nt*8*CINP2 + ks*8 + 4];
                MMA16(acc[nt], Ah, bh0, bh1);
                MMA16(acc[nt], Ah, bl0, bl1);
                MMA16(acc[nt], Al, bh0, bh1);
            }
        }
        const int g = lane >> 2, c = lane & 3;
        const int coA = co0 + g, coB = coA + 8;
        bf16* x2h = (bf16*)X2H; bf16* x2l = (bf16*)X2L;
        #pragma unroll
        for (int nt = 0; nt < 2; ++nt) {
            int px = pn0 + nt*8 + 2*c;
            float v0 = lrelu(acc[nt][0]), v1 = lrelu(acc[nt][1]);
            float v2 = lrelu(acc[nt][2]), v3 = lrelu(acc[nt][3]);
            bf16 h, l;
            split1(v0, h, l); x2h[(px  )*40 + coA] = h; x2l[(px  )*40 + coA] = l;
            split1(v1, h, l); x2h[(px+1)*40 + coA] = h; x2l[(px+1)*40 + coA] = l;
            split1(v2, h, l); x2h[(px  )*40 + coB] = h; x2l[(px  )*40 + coB] = l;
            split1(v3, h, l); x2h[(px+1)*40 + coB] = h; x2l[(px+1)*40 + coB] = l;
        }
    }
    __syncthreads();

    // ---- GEMM2: 72 rows x 128 px ----
    const int bcol = lane & 3;
    const int g = lane >> 2, c = lane & 3;
    // pass 1: rows 0-63, 16 warps (4 M x 4 N-tiles of 32px)
    {
        const int mt = wid % 4, nh = wid / 4;
        const int co0 = mt*16, pn0 = nh*32;
        const int arow = co0 + (lane & 7) + ((lane >> 3) & 1)*8;
        const int acw  = ((lane >> 4) & 1)*4;
        const u32 aBH = smem_u32(&W2H[arow*C2P2 + acw]);
        const u32 aBL = smem_u32(&W2L[arow*C2P2 + acw]);
        const int brow = pn0 + (lane >> 2);
        const u32* bXH = &X2H[brow*C2P2 + bcol];
        const u32* bXL = &X2L[brow*C2P2 + bcol];
        float acc[4][4];
        #pragma unroll
        for (int n = 0; n < 4; ++n) { acc[n][0]=0.f; acc[n][1]=0.f; acc[n][2]=0.f; acc[n][3]=0.f; }
        #pragma unroll
        for (int ks = 0; ks < 2; ++ks) {
            u32 Ah[4], Al[4];
            LDMX4(Ah, aBH + ks*32);
            LDMX4(Al, aBL + ks*32);
            #pragma unroll
            for (int nt = 0; nt < 4; ++nt) {
                u32 bh0 = bXH[nt*8*C2P2 + ks*8], bh1 = bXH[nt*8*C2P2 + ks*8 + 4];
                u32 bl0 = bXL[nt*8*C2P2 + ks*8], bl1 = bXL[nt*8*C2P2 + ks*8 + 4];
                MMA16(acc[nt], Ah, bh0, bh1);
                MMA16(acc[nt], Ah, bl0, bl1);
                MMA16(acc[nt], Al, bh0, bh1);
            }
        }
        const int coA = co0 + g, coB = coA + 8;
        const float bvA = SB[coA], bvB = SB[coB];
        #pragma unroll
        for (int nt = 0; nt < 4; ++nt) {
            int px = pxb + pn0 + nt*8 + 2*c;
            *(float2*)(of + ((size_t)b*72 + coA)*HW + px) = make_float2(acc[nt][0]+bvA, acc[nt][1]+bvA);
            *(float2*)(of + ((size_t)b*72 + coB)*HW + px) = make_float2(acc[nt][2]+bvB, acc[nt][3]+bvB);
        }
    }
    // pass 2: rows 64-71, warps 0-3 (coB rows 72-79 padding, skipped)
    if (wid < 4) {
        const int pn0 = wid*32;
        const int arow = 64 + (lane & 7) + ((lane >> 3) & 1)*8;
        const int acw  = ((lane >> 4) & 1)*4;
        const u32 aBH = smem_u32(&W2H[arow*C2P2 + acw]);
        const u32 aBL = smem_u32(&W2L[arow*C2P2 + acw]);
        const int brow = pn0 + (lane >> 2);
        const u32* bXH = &X2H[brow*C2P2 + bcol];
        const u32* bXL = &X2L[brow*C2P2 + bcol];
        float acc[4][4];
        #pragma unroll
        for (int n = 0; n < 4; ++n) { acc[n][0]=0.f; acc[n][1]=0.f; acc[n][2]=0.f; acc[n][3]=0.f; }
        #pragma unroll
        for (int ks = 0; ks < 2; ++ks) {
            u32 Ah[4], Al[4];
            LDMX4(Ah, aBH + ks*32);
            LDMX4(Al, aBL + ks*32);
            #pragma unroll
            for (int nt = 0; nt < 4; ++nt) {
                u32 bh0 = bXH[nt*8*C2P2 + ks*8], bh1 = bXH[nt*8*C2P2 + ks*8 + 4];
                u32 bl0 = bXL[nt*8*C2P2 + ks*8], bl1 = bXL[nt*8*C2P2 + ks*8 + 4];
                MMA16(acc[nt], Ah, bh0, bh1);
                MMA16(acc[nt], Ah, bl0, bl1);
                MMA16(acc[nt], Al, bh0, bh1);
            }
        }
        const int coA = 64 + g;
        const float bvA = SB[coA];
        #pragma unroll
        for (int nt = 0; nt < 4; ++nt) {
            int px = pxb + pn0 + nt*8 + 2*c;
            *(float2*)(of + ((size_t)b*72 + coA)*HW + px) = make_float2(acc[nt][0]+bvA, acc[nt][1]+bvA);
        }
    }
}

// ---------------- HMMA pointwise GEMM (sec), NT-parameterized ---------------
template<int C1, int C2, int COUT, int MT, int NWARP, bool LRELU>
__global__ void __launch_bounds__(NWARP*32, 1) pw_hmma(
    const bf16* __restrict__ p1h, const bf16* __restrict__ p1l,
    const bf16* __restrict__ p2h, const bf16* __restrict__ p2l,
    const float* __restrict__ Wt, const float* __restrict__ bias,
    float* __restrict__ of)
{
    constexpr int CIN = C1 + C2, KP2 = CIN/2;
    constexpr int CINP2 = (CIN == 128) ? 68 : (CIN == 64) ? 36 : 20;
    constexpr int COP = MT*16, NTH = NWARP*32, KS = CIN/16;
    constexpr int NTILES = NWARP/MT, NPX = 128/NTILES, NTL = NPX/8;

    extern __shared__ u32 sm[];
    u32* XH = sm;
    u32* XL = XH + 128*CINP2;
    u32* WH = XL + 128*CINP2;
    u32* WL = WH + COP*CINP2;
    float* SB = (float*)(WL + COP*CINP2);

    const int tid = threadIdx.x, lane = tid & 31, wid = tid >> 5;
    const int b = blockIdx.y, pxb = blockIdx.x * 128;

    stage_x<C1,C2,CINP2,NWARP>(XH, XL, p1h, p1l, p2h, p2l, b, pxb, lane, wid);

    for (int i = tid; i < COP*KP2; i += NTH) {
        int co = i / KP2, cp = i - co*KP2;
        float2 wv = make_float2(0.f, 0.f);
        if (co < COUT) wv = *(const float2*)(Wt + (size_t)co*CIN + 2*cp);
        u32 H, L; split2(wv.x, wv.y, H, L);
        WH[co*CINP2 + cp] = H; WL[co*CINP2 + cp] = L;
    }
    if (tid < COP) SB[tid] = (bias && tid < COUT) ? bias[tid] : 0.f;
    __syncthreads();

    const int mt = wid % MT, nh = wid / MT;
    const int co0 = mt*16, pn0 = nh*NPX;
    float acc[NTL][4];
    #pragma unroll
    for (int n = 0; n < NTL; ++n) { acc[n][0]=0.f; acc[n][1]=0.f; acc[n][2]=0.f; acc[n][3]=0.f; }

    const int arow = co0 + (lane & 7) + ((lane >> 3) & 1)*8;
    const int acw  = ((lane >> 4) & 1)*4;
    const u32 aBH = smem_u32(&WH[arow*CINP2 + acw]);
    const u32 aBL = smem_u32(&WL[arow*CINP2 + acw]);
    const int brow = pn0 + (lane >> 2), bcol = lane & 3;
    const u32* bXH = &XH[brow*CINP2 + bcol];
    const u32* bXL = &XL[brow*CINP2 + bcol];

    #pragma unroll
    for (int ks = 0; ks < KS; ++ks) {
        u32 Ah[4], Al[4];
        LDMX4(Ah, aBH + ks*32);
        LDMX4(Al, aBL + ks*32);
        #pragma unroll
        for (int nt = 0; nt < NTL; ++nt) {
            u32 bh0 = bXH[nt*8*CINP2 + ks*8], bh1 = bXH[nt*8*CINP2 + ks*8 + 4];
            u32 bl0 = bXL[nt*8*CINP2 + ks*8], bl1 = bXL[nt*8*CINP2 + ks*8 + 4];
            MMA16(acc[nt], Ah, bh0, bh1);
            MMA16(acc[nt], Ah, bl0, bl1);
            MMA16(acc[nt], Al, bh0, bh1);
        }
    }

    const int g = lane >> 2, c = lane & 3;
    const int coA = co0 + g, coB = coA + 8;
    const float bvA = SB[coA], bvB = SB[coB];
    #pragma unroll
    for (int nt = 0; nt < NTL; ++nt) {
        int px = pxb + pn0 + nt*8 + 2*c;
        float v0 = acc[nt][0] + bvA, v1 = acc[nt][1] + bvA;
        float v2 = acc[nt][2] + bvB, v3 = acc[nt][3] + bvB;
        if (LRELU) { v0=lrelu(v0); v1=lrelu(v1); v2=lrelu(v2); v3=lrelu(v3); }
        if (coA < COUT) *(float2*)(of + ((size_t)b*COUT + coA)*HW + px) = make_float2(v0,v1);
        if (coB < COUT) *(float2*)(of + ((size_t)b*COUT + coB)*HW + px) = make_float2(v2,v3);
    }
}

// ---------------- FFMA2 helpers ---------------------------------------------
__device__ __forceinline__ u64 pk2(float a, float b) { u64 r; asm("mov.b64 %0,{%1,%2};" : "=l"(r) : "f"(a), "f"(b)); return r; }
__device__ __forceinline__ u64 splat2(float a) { u64 r; asm("mov.b64 %0,{%1,%1};" : "=l"(r) : "f"(a)); return r; }
__device__ __forceinline__ u64 ffma2(u64 a, u64 b, u64 c) { u64 d; asm("fma.rn.f32x2 %0,%1,%2,%3;" : "=l"(d) : "l"(a), "l"(b), "l"(c)); return d; }
__device__ __forceinline__ float2 upk(u64 v) { float2 f; asm("mov.b64 {%0,%1},%2;" : "=f"(f.x), "=f"(f.y) : "l"(v)); return f; }

// ---------------- grouped 3x3 conv + lrelu -> split bf16 --------------------
__global__ void __launch_bounds__(256) gconv2_kernel(
    const float* __restrict__ in, const float* __restrict__ ke,
    bf16* __restrict__ oh, bf16* __restrict__ ol)
{
    __shared__ float sIn[16][18][34];
    __shared__ float sWt[16*9*16];
    const int tid = threadIdx.x;
    const int g = blockIdx.y, b = blockIdx.z;
    const int x0 = (blockIdx.x & 3)*32, y0 = (blockIdx.x >> 2)*16;
    const float* inb = in + ((size_t)(b*CC) + g*16)*HW;
    const float* kep = ke + (size_t)g*2304;

    for (int i = tid; i < 2304; i += 256) {
        int co = i/144, rem = i - co*144, ci = rem/9, t = rem - ci*9;
        sWt[(ci*9 + t)*16 + co] = kep[i];
    }
    for (int idx = tid; idx < 16*18*9; idx += 256) {
        int s = idx % 9, cr = idx / 9, c = cr/18, r = cr % 18, gy = y0 - 1 + r;
        bool yok = ((unsigned)gy < 128u);
        const float* row = inb + (size_t)c*HW + gy*WW;
        if (s < 8) {
            int j = 1 + 4*s;
            float4 v = yok ? *(const float4*)(row + x0 + 4*s) : make_float4(0,0,0,0);
            sIn[c][r][j]=v.x; sIn[c][r][j+1]=v.y; sIn[c][r][j+2]=v.z; sIn[c][r][j+3]=v.w;
        } else {
            sIn[c][r][0]  = (yok && x0-1 >= 0) ? row[x0-1] : 0.f;
            sIn[c][r][33] = (yok && x0+32 < 128) ? row[x0+32] : 0.f;
        }
    }
    __syncthreads();

    const int tx = tid & 31, ty = tid >> 5;
    u64 accA[8], accB[8];
    #pragma unroll
    for (int j = 0; j < 8; ++j) { accA[j]=0ull; accB[j]=0ull; }
    #pragma unroll 1
    for (int ci = 0; ci < 16; ++ci)
        #pragma unroll
        for (int kh = 0; kh < 3; ++kh) {
            u64 As[3] = { splat2(sIn[ci][ty+kh][tx]),   splat2(sIn[ci][ty+kh][tx+1]),   splat2(sIn[ci][ty+kh][tx+2]) };
            u64 Bs[3] = { splat2(sIn[ci][ty+8+kh][tx]), splat2(sIn[ci][ty+8+kh][tx+1]), splat2(sIn[ci][ty+8+kh][tx+2]) };
            const float* wb = &sWt[(ci*9 + kh*3)*16];
            #pragma unroll
            for (int kw = 0; kw < 3; ++kw) {
                const float* w = wb + kw*16;
                #pragma unroll
                for (int jp = 0; jp < 8; jp += 2) {
                    float4 w4 = *(const float4*)(w + 2*jp);
                    u64 wp0 = pk2(w4.x, w4.y), wp1 = pk2(w4.z, w4.w);
                    accA[jp]   = ffma2(As[kw], wp0, accA[jp]);
                    accA[jp+1] = ffma2(As[kw], wp1, accA[jp+1]);
                    accB[jp]   = ffma2(Bs[kw], wp0, accB[jp]);
                    accB[jp+1] = ffma2(Bs[kw], wp1, accB[jp+1]);
                }
            }
        }
    const int yA = y0 + ty, yB = y0 + ty + 8, x = x0 + tx;
    #pragma unroll
    for (int jp = 0; jp < 8; ++jp) {
        float2 a = upk(accA[jp]), bb = upk(accB[jp]);
        size_t c0 = ((size_t)(b*CC) + g*16 + 2*jp)*HW, c1 = c0 + HW;
        bf16 h,l;
        split1(lrelu(a.x),  h,l); oh[c0 + yA*WW + x] = h; ol[c0 + yA*WW + x] = l;
        split1(lrelu(a.y),  h,l); oh[c1 + yA*WW + x] = h; ol[c1 + yA*WW + x] = l;
        split1(lrelu(bb.x), h,l); oh[c0 + yB*WW + x] = h; ol[c0 + yB*WW + x] = l;
        split1(lrelu(bb.y), h,l); oh[c1 + yB*WW + x] = h; ol[c1 + yB*WW + x] = l;
    }
}

// ---------------- per-pixel dynamic local conv ------------------------------
template<bool RES, bool SPLIT>
__global__ void __launch_bounds__(256) localconv2_kernel(
    const float* __restrict__ in, const float* __restrict__ wb,
    const float* __restrict__ res, float* __restrict__ out,
    bf16* __restrict__ oh, bf16* __restrict__ ol)
{
    __shared__ float sh[8][10][34];
    const int tid = threadIdx.x, b = blockIdx.y;
    const int x0 = (blockIdx.x & 3)*32, y0 = (blockIdx.x >> 2)*8;
    const int tx = tid & 31, ty = tid >> 5;
    const int pix = (y0 + ty)*WW + x0 + tx;
    const float* inb = in + (size_t)b*CC*HW;
    const float* wbb = wb + (size_t)b*72*HW + pix;
    const float* rb  = RES ? res + (size_t)b*CC*HW + pix : nullptr;

    #pragma unroll 1
    for (int kg = 0; kg < 8; ++kg) {
        __syncthreads();
        const float* cb = inb + (size_t)kg*8*HW;
        for (int idx = tid; idx < 8*10*9; idx += 256) {
            int s = idx % 9, cr = idx / 9, c = cr/10, r = cr % 10, gy = y0 - 1 + r;
            bool yok = ((unsigned)gy < 128u);
            const float* row = cb + (size_t)c*HW + gy*WW;
            if (s < 8) {
                int j = 1 + 4*s;
                float4 v = yok ? *(const float4*)(row + x0 + 4*s) : make_float4(0,0,0,0);
                sh[c][r][j]=v.x; sh[c][r][j+1]=v.y; sh[c][r][j+2]=v.z; sh[c][r][j+3]=v.w;
            } else {
                sh[c][r][0]  = (yok && x0-1 >= 0) ? row[x0-1] : 0.f;
                sh[c][r][33] = (yok && x0+32 < 128) ? row[x0+32] : 0.f;
            }
        }
        __syncthreads();
        u64 ws[9];
        #pragma unroll
        for (int t = 0; t < 9; ++t) ws[t] = splat2(wbb[(size_t)(kg*9 + t)*HW]);
        #pragma unroll
        for (int cp = 0; cp < 4; ++cp) {
            const int c0 = 2*cp, ch = kg*8 + c0;
            u64 acc = RES ? pk2(rb[(size_t)ch*HW], rb[(size_t)(ch+1)*HW]) : 0ull;
            #pragma unroll
            for (int kh = 0; kh < 3; ++kh)
                #pragma unroll
                for (int kw = 0; kw < 3; ++kw)
                    acc = ffma2(pk2(sh[c0][ty+kh][tx+kw], sh[c0+1][ty+kh][tx+kw]), ws[kh*3+kw], acc);
            float2 r = upk(acc);
            size_t o0 = (size_t)(b*CC + ch)*HW + pix, o1 = o0 + HW;
            if (SPLIT) {
                bf16 h,l;
                split1(r.x,h,l); oh[o0]=h; ol[o0]=l;
                split1(r.y,h,l); oh[o1]=h; ol[o1]=l;
            } else { out[o0] = r.x; out[o1] = r.y; }
        }
    }
}

// ---------------- softmax over H --------------------------------------------
__global__ void __launch_bounds__(128) softmax_h(float* __restrict__ a)
{
    const int ch = blockIdx.x, b = blockIdx.y;
    float* col = a + ((size_t)(b*72) + ch)*HW + threadIdx.x;
    float m = -1e30f;
    #pragma unroll 4
    for (int h = 0; h < 128; ++h) m = fmaxf(m, col[h*WW]);
    float s = 0.f;
    #pragma unroll 4
    for (int h = 0; h < 128; ++h) s += __expf(col[h*WW] - m);
    float inv = 1.f / s;
    #pragma unroll 4
    for (int h = 0; h < 128; ++h) col[h*WW] = __expf(col[h*WW] - m) * inv;
}

// ---------------- launch ----------------------------------------------------
extern "C" void kernel_launch(void* const* d_in, const int* in_sizes, int n_in,
                              void* d_out, int out_size)
{
    (void)in_sizes; (void)n_in; (void)out_size;
    const float* x     = (const float*)d_in[0];
    const float* phi_w = (const float*)d_in[1];
    const float* phi_b = (const float*)d_in[2];
    const float* th_w  = (const float*)d_in[3];
    const float* th_b  = (const float*)d_in[4];
    const float* ke_w  = (const float*)d_in[5];
    const float* e1_w  = (const float*)d_in[6];
    const float* e2_w  = (const float*)d_in[7];
    const float* e2_b  = (const float*)d_in[8];
    const float* c1_w  = (const float*)d_in[9];
    const float* sw1_w = (const float*)d_in[10];
    const float* sw2_w = (const float*)d_in[11];
    const float* sw2_b = (const float*)d_in[12];
    const float* sec_w = (const float*)d_in[13];
    const float* sec_b = (const float*)d_in[14];

    float *key0, *h0, *gg, *w72, *attn;
    bf16 *xh,*xl,*qh,*ql,*kh,*kl,*hh,*hl;
    cudaGetSymbolAddress((void**)&key0, g_key0);
    cudaGetSymbolAddress((void**)&h0,   g_h0);
    cudaGetSymbolAddress((void**)&gg,   g_gg);
    cudaGetSymbolAddress((void**)&w72,  g_w72);
    cudaGetSymbolAddress((void**)&attn, g_attn);
    cudaGetSymbolAddress((void**)&xh, g_xh); cudaGetSymbolAddress((void**)&xl, g_xl);
    cudaGetSymbolAddress((void**)&qh, g_qh); cudaGetSymbolAddress((void**)&ql, g_ql);
    cudaGetSymbolAddress((void**)&kh, g_kh); cudaGetSymbolAddress((void**)&kl, g_kl);
    cudaGetSymbolAddress((void**)&hh, g_hh); cudaGetSymbolAddress((void**)&hl, g_hl);

    constexpr int SM_PW3 = (2*128*36 + 6*64*36)*4 + 192*4;
    constexpr int SM_FE  = (2*128*68 + 2*32*68 + 2*80*20 + 2*128*20)*4 + 80*4;
    constexpr int SM_SEC = (2*128*68 + 2*64*68)*4 + 64*4;

    cudaFuncSetAttribute(pw3_kernel,    cudaFuncAttributeMaxDynamicSharedMemorySize, SM_PW3);
    cudaFuncSetAttribute(fused_e_kernel,cudaFuncAttributeMaxDynamicSharedMemorySize, SM_FE);
    cudaFuncSetAttribute(pw_hmma<64,64,64,4,16,false>, cudaFuncAttributeMaxDynamicSharedMemorySize, SM_SEC);

    dim3 pg(128, BATCH);

    prep_x<<<4096, 512>>>(x, xh, xl);

    // key0 = phi(x); q = theta(x) [split]; h0 = c1(x)
    pw3_kernel<<<pg,512,SM_PW3>>>(xh,xl, phi_w,phi_b, th_w,th_b, c1_w, key0, qh,ql, h0);

    // key = lrelu(gconv(key0)) [split]
    gconv2_kernel<<<dim3(32,4,BATCH),256>>>(key0, ke_w, kh, kl);

    // w72 = e2(lrelu(e1([q,k])))
    fused_e_kernel<<<pg,512,SM_FE>>>(qh,ql, kh,kl, e1_w, e2_w, e2_b, w72);

    // h1 = local_conv(h0, w72) [split]
    localconv2_kernel<false,true><<<dim3(64,BATCH),256>>>(h0, w72, nullptr, nullptr, hh, hl);

    // attn = softmax_H(sw2(lrelu(sw1([h1,k]))))
    fused_e_kernel<<<pg,512,SM_FE>>>(hh,hl, kh,kl, sw1_w, sw2_w, sw2_b, attn);
    softmax_h<<<dim3(72,BATCH),128>>>(attn);

    // out = local_conv(sec([h1,k]), attn) + x
    pw_hmma<64,64,64,4,16,false><<<pg,512,SM_SEC>>>(hh,hl, kh,kl, sec_w, sec_b, gg);
    localconv2_kernel<true,false><<<dim3(64,BATCH),256>>>(gg, attn, x, (float*)d_out, nullptr,nullptr);
}